// round 3
// baseline (speedup 1.0000x reference)
#include <cuda_runtime.h>
#include <math.h>

// Problem constants (fixed by setup_inputs)
#define MAXN 50000
#define MAXE 1600000

// ---------------- device scratch (globals: allocation-free rule) -----------
__device__ __align__(16) float g_h1 [MAXN * 64];  // layer1 linear out  [N,64]
__device__ __align__(16) float g_as1[MAXN * 8];   // a_src layer1       [N,8]
__device__ __align__(16) float g_ad1[MAXN * 8];   // a_dst layer1       [N,8]
__device__ __align__(16) float g_h1p[MAXN * 64];  // layer1 output (post bias+elu)
__device__ __align__(16) float g_h2 [MAXN * 64];  // layer2 linear out
__device__ __align__(16) float g_as2[MAXN];
__device__ __align__(16) float g_ad2[MAXN];
__device__ int g_srce[MAXE];                      // edge src as int32
__device__ int g_dste[MAXE];                      // edge dst as int32
__device__ int g_cnt [MAXN];
__device__ int g_cur [MAXN];
__device__ int g_offs[MAXN + 1];
__device__ int g_ebuf[MAXE];                      // src node id per CSR slot
__device__ int g_is64;

// ---------------- edge index dtype detect + convert -------------------------
// int64 storage: value v (0 <= v < 50000) occupies words {lo=v, hi=0}.
// OR of odd words over a sample is 0 iff int64. For int32, odd words are
// random node ids -> OR is nonzero with overwhelming probability.
__global__ void detect_kernel(const int* __restrict__ ei32, int E) {
    __shared__ int s_or;
    if (threadIdx.x == 0) s_or = 0;
    __syncthreads();
    int acc = 0;
    int nsamp = (E < 4096) ? E : 4096;
    for (int i = threadIdx.x; i < nsamp; i += blockDim.x)
        acc |= ei32[2 * i + 1];
    atomicOr(&s_or, acc);
    __syncthreads();
    if (threadIdx.x == 0) g_is64 = (s_or == 0) ? 1 : 0;
}

__global__ void convert_kernel(const void* __restrict__ ei, int E) {
    int i = blockIdx.x * blockDim.x + threadIdx.x;
    if (i >= E) return;
    int s, d;
    if (g_is64) {
        const long long* e64 = (const long long*)ei;
        s = (int)e64[i];
        d = (int)e64[E + i];
    } else {
        const int* e32 = (const int*)ei;
        s = e32[i];
        d = e32[E + i];
    }
    g_srce[i] = s;
    g_dste[i] = d;
}

// ---------------- CSR build -------------------------------------------------
__global__ void zero_kernel(int N) {
    int i = blockIdx.x * blockDim.x + threadIdx.x;
    if (i < N) { g_cnt[i] = 0; g_cur[i] = 0; }
}

__global__ void count_kernel(int E, int N) {
    int i = blockIdx.x * blockDim.x + threadIdx.x;
    if (i < E) {
        int d = g_dste[i];
        if ((unsigned)d < (unsigned)N) atomicAdd(&g_cnt[d], 1);
    }
}

__global__ void scan_kernel(int N) {
    __shared__ int s[1024];
    __shared__ int run_s;
    int tid = threadIdx.x;
    if (tid == 0) run_s = 0;
    __syncthreads();
    for (int base = 0; base < N; base += 1024) {
        int v = (base + tid < N) ? g_cnt[base + tid] : 0;
        s[tid] = v;
        __syncthreads();
        #pragma unroll
        for (int off = 1; off < 1024; off <<= 1) {
            int t = (tid >= off) ? s[tid - off] : 0;
            __syncthreads();
            s[tid] += t;
            __syncthreads();
        }
        if (base + tid < N) g_offs[base + tid] = run_s + s[tid] - v;
        __syncthreads();
        if (tid == 0) run_s += s[1023];
        __syncthreads();
    }
    if (tid == 0) g_offs[N] = run_s;
}

__global__ void scatter_kernel(int E, int N) {
    int i = blockIdx.x * blockDim.x + threadIdx.x;
    if (i < E) {
        int d = g_dste[i];
        if ((unsigned)d < (unsigned)N) {
            int p = atomicAdd(&g_cur[d], 1);
            g_ebuf[g_offs[d] + p] = g_srce[i];
        }
    }
}

// ---------------- layer 1 GEMM: h1 = x @ W1, + a_src1/a_dst1 ---------------
// x [N,256], W1 [256,64]. Block: 32 rows, 256 threads.
// smem: W1 (64KB) + x tile (32KB) = 96KB dynamic.
__global__ void gemm1_kernel(const float* __restrict__ x, const float* __restrict__ W,
                             const float* __restrict__ att_s, const float* __restrict__ att_d,
                             int N) {
    extern __shared__ float sm[];
    float4* Ws4 = (float4*)sm;              // 4096 float4 (256x64)
    float4* xs4 = (float4*)(sm + 256 * 64); // 2048 float4 (32x256)
    int tid = threadIdx.x;

    const float4* Wg4 = (const float4*)W;
    #pragma unroll
    for (int i = 0; i < 16; i++) Ws4[tid + i * 256] = Wg4[tid + i * 256];

    int r0 = blockIdx.x * 32;
    const float4* xg4 = (const float4*)(x + (size_t)r0 * 256);
    int rows = N - r0; if (rows > 32) rows = 32;
    int nf4 = rows * 64;
    #pragma unroll
    for (int i = 0; i < 8; i++) {
        int idx = tid + i * 256;
        xs4[idx] = (idx < nf4) ? xg4[idx] : make_float4(0.f, 0.f, 0.f, 0.f);
    }
    __syncthreads();

    int r = tid >> 3, cg = tid & 7;
    float acc[8];
    #pragma unroll
    for (int j = 0; j < 8; j++) acc[j] = 0.f;

    const float4* xr4 = xs4 + r * 64;
    #pragma unroll 4
    for (int k4 = 0; k4 < 64; k4++) {
        float4 xv = xr4[k4];
        float xk[4] = {xv.x, xv.y, xv.z, xv.w};
        #pragma unroll
        for (int u = 0; u < 4; u++) {
            int k = k4 * 4 + u;
            float4 w0 = Ws4[k * 16 + cg * 2];
            float4 w1 = Ws4[k * 16 + cg * 2 + 1];
            float xvv = xk[u];
            acc[0] = fmaf(xvv, w0.x, acc[0]); acc[1] = fmaf(xvv, w0.y, acc[1]);
            acc[2] = fmaf(xvv, w0.z, acc[2]); acc[3] = fmaf(xvv, w0.w, acc[3]);
            acc[4] = fmaf(xvv, w1.x, acc[4]); acc[5] = fmaf(xvv, w1.y, acc[5]);
            acc[6] = fmaf(xvv, w1.z, acc[6]); acc[7] = fmaf(xvv, w1.w, acc[7]);
        }
    }

    int row = r0 + r;
    if (row < N) {
        float4* o4 = (float4*)(g_h1 + (size_t)row * 64 + cg * 8);
        o4[0] = make_float4(acc[0], acc[1], acc[2], acc[3]);
        o4[1] = make_float4(acc[4], acc[5], acc[6], acc[7]);
        float as = 0.f, ad = 0.f;
        #pragma unroll
        for (int j = 0; j < 8; j++) {
            as = fmaf(acc[j], att_s[cg * 8 + j], as);
            ad = fmaf(acc[j], att_d[cg * 8 + j], ad);
        }
        g_as1[row * 8 + cg] = as;
        g_ad1[row * 8 + cg] = ad;
    }
}

// ---------------- layer 1 aggregation: warp per dst, fused softmax+bias+elu
__global__ void agg1_kernel(const float* __restrict__ bias1, int N) {
    int warp = (blockIdx.x * blockDim.x + threadIdx.x) >> 5;
    int lane = threadIdx.x & 31;
    if (warp >= N) return;
    int dst = warp;
    int head = lane >> 2;                 // lane covers channels 2*lane, 2*lane+1
    float ad = g_ad1[dst * 8 + head];
    int beg = g_offs[dst], end = g_offs[dst + 1];

    float den = 0.f, ax = 0.f, ay = 0.f;
    const float2* h1f2 = (const float2*)g_h1;
    #pragma unroll 4
    for (int i = beg; i < end; i++) {
        int s = g_ebuf[i];
        float e = g_as1[s * 8 + head] + ad;
        e = (e > 0.f) ? e : 0.2f * e;
        float w = __expf(e);
        float2 hv = h1f2[(size_t)s * 32 + lane];
        den += w;
        ax = fmaf(w, hv.x, ax);
        ay = fmaf(w, hv.y, ay);
    }
    float inv = 1.f / (den + 1e-16f);
    int c0 = lane * 2;
    float v0 = fmaf(ax, inv, bias1[c0]);
    float v1 = fmaf(ay, inv, bias1[c0 + 1]);
    v0 = (v0 > 0.f) ? v0 : expm1f(v0);    // elu
    v1 = (v1 > 0.f) ? v1 : expm1f(v1);
    ((float2*)g_h1p)[(size_t)dst * 32 + lane] = make_float2(v0, v1);
}

// ---------------- layer 2 GEMM: h2 = h1p @ W2, + a_src2/a_dst2 -------------
__global__ void gemm2_kernel(const float* __restrict__ W2,
                             const float* __restrict__ att_s2, const float* __restrict__ att_d2,
                             int N) {
    __shared__ float Ws[64 * 64];
    __shared__ float xs[32 * 64];
    int tid = threadIdx.x;

    float4* Ws4 = (float4*)Ws;
    const float4* Wg4 = (const float4*)W2;
    #pragma unroll
    for (int i = 0; i < 4; i++) Ws4[tid + i * 256] = Wg4[tid + i * 256];

    int r0 = blockIdx.x * 32;
    float4* xs4 = (float4*)xs;
    const float4* xg4 = (const float4*)(g_h1p + (size_t)r0 * 64);
    int rows = N - r0; if (rows > 32) rows = 32;
    int nf4 = rows * 16;
    #pragma unroll
    for (int i = 0; i < 2; i++) {
        int idx = tid + i * 256;
        xs4[idx] = (idx < nf4) ? xg4[idx] : make_float4(0.f, 0.f, 0.f, 0.f);
    }
    __syncthreads();

    int r = tid >> 3, cg = tid & 7;
    float acc[8];
    #pragma unroll
    for (int j = 0; j < 8; j++) acc[j] = 0.f;
    const float* xr = xs + r * 64;
    #pragma unroll 8
    for (int k = 0; k < 64; k++) {
        float xv = xr[k];
        float4 w0 = Ws4[k * 16 + cg * 2];
        float4 w1 = Ws4[k * 16 + cg * 2 + 1];
        acc[0] = fmaf(xv, w0.x, acc[0]); acc[1] = fmaf(xv, w0.y, acc[1]);
        acc[2] = fmaf(xv, w0.z, acc[2]); acc[3] = fmaf(xv, w0.w, acc[3]);
        acc[4] = fmaf(xv, w1.x, acc[4]); acc[5] = fmaf(xv, w1.y, acc[5]);
        acc[6] = fmaf(xv, w1.z, acc[6]); acc[7] = fmaf(xv, w1.w, acc[7]);
    }

    // attention partials (H=1, C=64): reduce over the 8 threads of this row
    float ps = 0.f, pd = 0.f;
    #pragma unroll
    for (int j = 0; j < 8; j++) {
        ps = fmaf(acc[j], att_s2[cg * 8 + j], ps);
        pd = fmaf(acc[j], att_d2[cg * 8 + j], pd);
    }
    #pragma unroll
    for (int o = 4; o >= 1; o >>= 1) {
        ps += __shfl_down_sync(0xffffffffu, ps, o);
        pd += __shfl_down_sync(0xffffffffu, pd, o);
    }

    int row = r0 + r;
    if (row < N) {
        float4* o4 = (float4*)(g_h2 + (size_t)row * 64 + cg * 8);
        o4[0] = make_float4(acc[0], acc[1], acc[2], acc[3]);
        o4[1] = make_float4(acc[4], acc[5], acc[6], acc[7]);
        if (cg == 0) { g_as2[row] = ps; g_ad2[row] = pd; }
    }
}

// ---------------- layer 2 aggregation + bias + log_softmax -> d_out --------
__global__ void agg2_kernel(const float* __restrict__ bias2, float* __restrict__ out, int N) {
    int warp = (blockIdx.x * blockDim.x + threadIdx.x) >> 5;
    int lane = threadIdx.x & 31;
    if (warp >= N) return;
    int dst = warp;
    float ad = g_ad2[dst];
    int beg = g_offs[dst], end = g_offs[dst + 1];

    float den = 0.f, ax = 0.f, ay = 0.f;
    const float2* h2f2 = (const float2*)g_h2;
    #pragma unroll 4
    for (int i = beg; i < end; i++) {
        int s = g_ebuf[i];
        float e = g_as2[s] + ad;
        e = (e > 0.f) ? e : 0.2f * e;
        float w = __expf(e);
        float2 hv = h2f2[(size_t)s * 32 + lane];
        den += w;
        ax = fmaf(w, hv.x, ax);
        ay = fmaf(w, hv.y, ay);
    }
    float inv = 1.f / (den + 1e-16f);
    int c0 = lane * 2;
    float v0 = fmaf(ax, inv, bias2[c0]);
    float v1 = fmaf(ay, inv, bias2[c0 + 1]);

    // log_softmax over 64 values spread 2-per-lane across the warp
    float m = fmaxf(v0, v1);
    #pragma unroll
    for (int o = 16; o >= 1; o >>= 1) m = fmaxf(m, __shfl_xor_sync(0xffffffffu, m, o));
    float se = __expf(v0 - m) + __expf(v1 - m);
    #pragma unroll
    for (int o = 16; o >= 1; o >>= 1) se += __shfl_xor_sync(0xffffffffu, se, o);
    float lse = m + logf(se);

    ((float2*)out)[(size_t)dst * 32 + lane] = make_float2(v0 - lse, v1 - lse);
}

// ---------------- launch ----------------------------------------------------
extern "C" void kernel_launch(void* const* d_in, const int* in_sizes, int n_in,
                              void* d_out, int out_size) {
    const float* x      = (const float*)d_in[0];
    const void*  ei     = d_in[1];
    const float* W1     = (const float*)d_in[2];
    const float* atts1  = (const float*)d_in[3];
    const float* attd1  = (const float*)d_in[4];
    const float* bias1  = (const float*)d_in[5];
    const float* W2     = (const float*)d_in[6];
    const float* atts2  = (const float*)d_in[7];
    const float* attd2  = (const float*)d_in[8];
    const float* bias2  = (const float*)d_in[9];
    float* out = (float*)d_out;

    int N = in_sizes[0] / 256;
    int E = in_sizes[1] / 2;

    // edge-index dtype detect + convert to int32 SoA
    detect_kernel <<<1, 256>>>((const int*)ei, E);
    convert_kernel<<<(E + 255) / 256, 256>>>(ei, E);

    // CSR build (per launch; deterministic work, atomic order noise << 1e-3)
    zero_kernel   <<<(N + 255) / 256, 256>>>(N);
    count_kernel  <<<(E + 255) / 256, 256>>>(E, N);
    scan_kernel   <<<1, 1024>>>(N);
    scatter_kernel<<<(E + 255) / 256, 256>>>(E, N);

    // layer 1
    cudaFuncSetAttribute(gemm1_kernel, cudaFuncAttributeMaxDynamicSharedMemorySize, 98304);
    gemm1_kernel<<<(N + 31) / 32, 256, 98304>>>(x, W1, atts1, attd1, N);
    agg1_kernel <<<(N + 7) / 8, 256>>>(bias1, N);

    // layer 2
    gemm2_kernel<<<(N + 31) / 32, 256>>>(W2, atts2, attd2, N);
    agg2_kernel <<<(N + 7) / 8, 256>>>(bias2, out, N);
}

// round 4
// speedup vs baseline: 1.7101x; 1.7101x over previous
#include <cuda_runtime.h>
#include <math.h>

// Problem constants (fixed by setup_inputs)
#define MAXN 50000
#define MAXE 1600000

typedef unsigned long long ull;

// ---------------- device scratch (globals: allocation-free rule) -----------
__device__ __align__(16) float g_h1 [MAXN * 64];  // layer1 linear out  [N,64]
__device__ __align__(16) float g_as1[MAXN * 8];   // a_src layer1       [N,8]
__device__ __align__(16) float g_ad1[MAXN * 8];   // a_dst layer1       [N,8]
__device__ __align__(16) float g_h1p[MAXN * 64];  // layer1 output (post bias+elu)
__device__ __align__(16) float g_h2 [MAXN * 64];  // layer2 linear out
__device__ __align__(16) float g_as2[MAXN];
__device__ __align__(16) float g_ad2[MAXN];
__device__ int g_srce[MAXE];                      // edge src as int32
__device__ int g_dste[MAXE];                      // edge dst as int32
__device__ int g_cnt [MAXN];
__device__ int g_cur [MAXN];
__device__ int g_offs[MAXN + 1];
__device__ int g_ebuf[MAXE];                      // src node id per CSR slot
__device__ int g_is64;

// packed f32x2 FMA (sm_103a: only reachable via PTX)
#define FMA_F32X2(d, a, b, c) \
    asm("fma.rn.f32x2 %0, %1, %2, %3;" : "=l"(d) : "l"(a), "l"(b), "l"(c))
#define PACK_DUP_F32X2(d, x) \
    asm("mov.b64 %0, {%1, %1};" : "=l"(d) : "r"(__float_as_uint(x)))
#define UNPACK_F32X2(lo, hi, in) \
    asm("mov.b64 {%0, %1}, %2;" : "=r"(lo), "=r"(hi) : "l"(in))

// ---------------- edge index dtype detect -----------------------------------
// int64 storage: small positive values -> every odd 32-bit word is 0.
__global__ void detect_kernel(const int* __restrict__ ei32, int E) {
    __shared__ int s_or;
    if (threadIdx.x == 0) s_or = 0;
    __syncthreads();
    int acc = 0;
    int nsamp = (E < 4096) ? E : 4096;
    for (int i = threadIdx.x; i < nsamp; i += blockDim.x)
        acc |= ei32[2 * i + 1];
    atomicOr(&s_or, acc);
    __syncthreads();
    if (threadIdx.x == 0) g_is64 = (s_or == 0) ? 1 : 0;
}

__global__ void zero_kernel(int N) {
    int i = blockIdx.x * blockDim.x + threadIdx.x;
    if (i < N) { g_cnt[i] = 0; g_cur[i] = 0; }
}

// fused convert (int64/int32 -> int32 SoA) + count of dst degrees
__global__ void convcount_kernel(const void* __restrict__ ei, int E, int N) {
    int i = blockIdx.x * blockDim.x + threadIdx.x;
    if (i >= E) return;
    int s, d;
    if (g_is64) {
        const long long* e64 = (const long long*)ei;
        s = (int)e64[i];
        d = (int)e64[E + i];
    } else {
        const int* e32 = (const int*)ei;
        s = e32[i];
        d = e32[E + i];
    }
    g_srce[i] = s;
    g_dste[i] = d;
    if ((unsigned)d < (unsigned)N) atomicAdd(&g_cnt[d], 1);
}

// warp-shuffle based exclusive scan (single block, 1024 threads)
__global__ void scan_kernel(int N) {
    __shared__ int wsum[32];
    __shared__ int run_s;
    int tid = threadIdx.x, lane = tid & 31, wid = tid >> 5;
    if (tid == 0) run_s = 0;
    __syncthreads();
    for (int base = 0; base < N; base += 1024) {
        int i = base + tid;
        int v = (i < N) ? g_cnt[i] : 0;
        int sc = v;
        #pragma unroll
        for (int o = 1; o < 32; o <<= 1) {
            int t = __shfl_up_sync(0xffffffffu, sc, o);
            if (lane >= o) sc += t;
        }
        if (lane == 31) wsum[wid] = sc;
        __syncthreads();
        if (wid == 0) {
            int s = wsum[lane];
            #pragma unroll
            for (int o = 1; o < 32; o <<= 1) {
                int t = __shfl_up_sync(0xffffffffu, s, o);
                if (lane >= o) s += t;
            }
            wsum[lane] = s;
        }
        __syncthreads();
        int add = ((wid > 0) ? wsum[wid - 1] : 0) + run_s;
        if (i < N) g_offs[i] = add + sc - v;
        __syncthreads();
        if (tid == 0) run_s += wsum[31];
        __syncthreads();
    }
    if (tid == 0) g_offs[N] = run_s;
}

__global__ void scatter_kernel(int E, int N) {
    int i = blockIdx.x * blockDim.x + threadIdx.x;
    if (i < E) {
        int d = g_dste[i];
        if ((unsigned)d < (unsigned)N) {
            int p = atomicAdd(&g_cur[d], 1);
            g_ebuf[g_offs[d] + p] = g_srce[i];
        }
    }
}

// ---------------- layer 1 GEMM: h1 = x @ W1 (f32x2 packed) ------------------
// Tile: 128 rows x 64 cols per block; k chunks of 64.
// Thread = 4 strided rows (lane, lane+32, lane+64, lane+96) x 8 cols (warp id).
// smem: Ws [64k][64c] 16KB + xs [128r][65] 33.3KB  (dynamic, ~49.7KB)
__global__ void __launch_bounds__(256) gemm1_kernel(
        const float* __restrict__ x, const float* __restrict__ W,
        const float* __restrict__ att_s, const float* __restrict__ att_d,
        int N) {
    extern __shared__ float sm[];
    float* Ws = sm;             // [k][col], row-major 64x64
    float* xs = sm + 64 * 64;   // [row][k], pad to 65

    int tid = threadIdx.x;
    int lane = tid & 31;
    int w = tid >> 5;           // warp id = col group = head
    int r0 = blockIdx.x * 128;

    ull acc[16];                // [row 4][colpair 4]
    #pragma unroll
    for (int i = 0; i < 16; i++) acc[i] = 0ull;

    for (int kc = 0; kc < 4; kc++) {
        int k0 = kc * 64;
        __syncthreads();
        // load W chunk: rows k0..k0+63 of W[256][64]  (1024 float4)
        #pragma unroll
        for (int i = 0; i < 4; i++) {
            int idx = tid + i * 256;
            ((float4*)Ws)[idx] = ((const float4*)W)[(k0 << 4) + idx];
        }
        // load x chunk: rows r0..r0+127, cols k0..k0+63 (2048 float4)
        #pragma unroll
        for (int p = 0; p < 8; p++) {
            int idx = tid + p * 256;
            int row = idx >> 4, f4 = idx & 15;
            int grow = r0 + row;
            float4 v = make_float4(0.f, 0.f, 0.f, 0.f);
            if (grow < N) v = ((const float4*)x)[(size_t)grow * 64 + (k0 >> 2) + f4];
            float* dp = &xs[row * 65 + f4 * 4];
            dp[0] = v.x; dp[1] = v.y; dp[2] = v.z; dp[3] = v.w;
        }
        __syncthreads();

        #pragma unroll 2
        for (int k = 0; k < 64; k++) {
            ull xp[4];
            #pragma unroll
            for (int rr = 0; rr < 4; rr++) {
                float xv = xs[(lane + rr * 32) * 65 + k];
                PACK_DUP_F32X2(xp[rr], xv);
            }
            const ull* wp = (const ull*)&Ws[k * 64 + w * 8];
            ull w0 = wp[0], w1 = wp[1], w2 = wp[2], w3 = wp[3];
            #pragma unroll
            for (int rr = 0; rr < 4; rr++) {
                FMA_F32X2(acc[rr * 4 + 0], xp[rr], w0, acc[rr * 4 + 0]);
                FMA_F32X2(acc[rr * 4 + 1], xp[rr], w1, acc[rr * 4 + 1]);
                FMA_F32X2(acc[rr * 4 + 2], xp[rr], w2, acc[rr * 4 + 2]);
                FMA_F32X2(acc[rr * 4 + 3], xp[rr], w3, acc[rr * 4 + 3]);
            }
        }
    }

    // epilogue: unpack, write h1 + attention partials (head == w)
    #pragma unroll
    for (int rr = 0; rr < 4; rr++) {
        int row = r0 + lane + rr * 32;
        if (row >= N) continue;
        float c[8];
        #pragma unroll
        for (int cp = 0; cp < 4; cp++) {
            unsigned lo, hi;
            UNPACK_F32X2(lo, hi, acc[rr * 4 + cp]);
            c[cp * 2]     = __uint_as_float(lo);
            c[cp * 2 + 1] = __uint_as_float(hi);
        }
        float4* o4 = (float4*)(g_h1 + (size_t)row * 64 + w * 8);
        o4[0] = make_float4(c[0], c[1], c[2], c[3]);
        o4[1] = make_float4(c[4], c[5], c[6], c[7]);
        float as = 0.f, ad = 0.f;
        #pragma unroll
        for (int j = 0; j < 8; j++) {
            as = fmaf(c[j], att_s[w * 8 + j], as);
            ad = fmaf(c[j], att_d[w * 8 + j], ad);
        }
        g_as1[row * 8 + w] = as;
        g_ad1[row * 8 + w] = ad;
    }
}

// ---------------- layer 1 aggregation: warp per dst, fused softmax+bias+elu
__global__ void agg1_kernel(const float* __restrict__ bias1, int N) {
    int warp = (blockIdx.x * blockDim.x + threadIdx.x) >> 5;
    int lane = threadIdx.x & 31;
    if (warp >= N) return;
    int dst = warp;
    int head = lane >> 2;
    float ad = g_ad1[dst * 8 + head];
    int beg = g_offs[dst], end = g_offs[dst + 1];

    float den = 0.f, ax = 0.f, ay = 0.f;
    const float2* h1f2 = (const float2*)g_h1;
    #pragma unroll 4
    for (int i = beg; i < end; i++) {
        int s = __ldg(&g_ebuf[i]);
        float e = __ldg(&g_as1[s * 8 + head]) + ad;
        e = (e > 0.f) ? e : 0.2f * e;
        float w = __expf(e);
        float2 hv = __ldg(&h1f2[(size_t)s * 32 + lane]);
        den += w;
        ax = fmaf(w, hv.x, ax);
        ay = fmaf(w, hv.y, ay);
    }
    float inv = 1.f / (den + 1e-16f);
    int c0 = lane * 2;
    float v0 = fmaf(ax, inv, bias1[c0]);
    float v1 = fmaf(ay, inv, bias1[c0 + 1]);
    v0 = (v0 > 0.f) ? v0 : expm1f(v0);
    v1 = (v1 > 0.f) ? v1 : expm1f(v1);
    ((float2*)g_h1p)[(size_t)dst * 32 + lane] = make_float2(v0, v1);
}

// ---------------- layer 2 GEMM: h2 = h1p @ W2, + a_src2/a_dst2 -------------
__global__ void gemm2_kernel(const float* __restrict__ W2,
                             const float* __restrict__ att_s2, const float* __restrict__ att_d2,
                             int N) {
    __shared__ float Ws[64 * 64];
    __shared__ float xs[32 * 64];
    int tid = threadIdx.x;

    float4* Ws4 = (float4*)Ws;
    const float4* Wg4 = (const float4*)W2;
    #pragma unroll
    for (int i = 0; i < 4; i++) Ws4[tid + i * 256] = Wg4[tid + i * 256];

    int r0 = blockIdx.x * 32;
    float4* xs4 = (float4*)xs;
    const float4* xg4 = (const float4*)(g_h1p + (size_t)r0 * 64);
    int rows = N - r0; if (rows > 32) rows = 32;
    int nf4 = rows * 16;
    #pragma unroll
    for (int i = 0; i < 2; i++) {
        int idx = tid + i * 256;
        xs4[idx] = (idx < nf4) ? xg4[idx] : make_float4(0.f, 0.f, 0.f, 0.f);
    }
    __syncthreads();

    int r = tid >> 3, cg = tid & 7;
    float acc[8];
    #pragma unroll
    for (int j = 0; j < 8; j++) acc[j] = 0.f;
    const float* xr = xs + r * 64;
    #pragma unroll 8
    for (int k = 0; k < 64; k++) {
        float xv = xr[k];
        float4 w0 = Ws4[k * 16 + cg * 2];
        float4 w1 = Ws4[k * 16 + cg * 2 + 1];
        acc[0] = fmaf(xv, w0.x, acc[0]); acc[1] = fmaf(xv, w0.y, acc[1]);
        acc[2] = fmaf(xv, w0.z, acc[2]); acc[3] = fmaf(xv, w0.w, acc[3]);
        acc[4] = fmaf(xv, w1.x, acc[4]); acc[5] = fmaf(xv, w1.y, acc[5]);
        acc[6] = fmaf(xv, w1.z, acc[6]); acc[7] = fmaf(xv, w1.w, acc[7]);
    }

    float ps = 0.f, pd = 0.f;
    #pragma unroll
    for (int j = 0; j < 8; j++) {
        ps = fmaf(acc[j], att_s2[cg * 8 + j], ps);
        pd = fmaf(acc[j], att_d2[cg * 8 + j], pd);
    }
    #pragma unroll
    for (int o = 4; o >= 1; o >>= 1) {
        ps += __shfl_down_sync(0xffffffffu, ps, o);
        pd += __shfl_down_sync(0xffffffffu, pd, o);
    }

    int row = r0 + r;
    if (row < N) {
        float4* o4 = (float4*)(g_h2 + (size_t)row * 64 + cg * 8);
        o4[0] = make_float4(acc[0], acc[1], acc[2], acc[3]);
        o4[1] = make_float4(acc[4], acc[5], acc[6], acc[7]);
        if (cg == 0) { g_as2[row] = ps; g_ad2[row] = pd; }
    }
}

// ---------------- layer 2 aggregation + bias + log_softmax -> d_out --------
__global__ void agg2_kernel(const float* __restrict__ bias2, float* __restrict__ out, int N) {
    int warp = (blockIdx.x * blockDim.x + threadIdx.x) >> 5;
    int lane = threadIdx.x & 31;
    if (warp >= N) return;
    int dst = warp;
    float ad = g_ad2[dst];
    int beg = g_offs[dst], end = g_offs[dst + 1];

    float den = 0.f, ax = 0.f, ay = 0.f;
    const float2* h2f2 = (const float2*)g_h2;
    #pragma unroll 4
    for (int i = beg; i < end; i++) {
        int s = __ldg(&g_ebuf[i]);
        float e = __ldg(&g_as2[s]) + ad;
        e = (e > 0.f) ? e : 0.2f * e;
        float w = __expf(e);
        float2 hv = __ldg(&h2f2[(size_t)s * 32 + lane]);
        den += w;
        ax = fmaf(w, hv.x, ax);
        ay = fmaf(w, hv.y, ay);
    }
    float inv = 1.f / (den + 1e-16f);
    int c0 = lane * 2;
    float v0 = fmaf(ax, inv, bias2[c0]);
    float v1 = fmaf(ay, inv, bias2[c0 + 1]);

    float m = fmaxf(v0, v1);
    #pragma unroll
    for (int o = 16; o >= 1; o >>= 1) m = fmaxf(m, __shfl_xor_sync(0xffffffffu, m, o));
    float se = __expf(v0 - m) + __expf(v1 - m);
    #pragma unroll
    for (int o = 16; o >= 1; o >>= 1) se += __shfl_xor_sync(0xffffffffu, se, o);
    float lse = m + logf(se);

    ((float2*)out)[(size_t)dst * 32 + lane] = make_float2(v0 - lse, v1 - lse);
}

// ---------------- launch ----------------------------------------------------
extern "C" void kernel_launch(void* const* d_in, const int* in_sizes, int n_in,
                              void* d_out, int out_size) {
    const float* x      = (const float*)d_in[0];
    const void*  ei     = d_in[1];
    const float* W1     = (const float*)d_in[2];
    const float* atts1  = (const float*)d_in[3];
    const float* attd1  = (const float*)d_in[4];
    const float* bias1  = (const float*)d_in[5];
    const float* W2     = (const float*)d_in[6];
    const float* atts2  = (const float*)d_in[7];
    const float* attd2  = (const float*)d_in[8];
    const float* bias2  = (const float*)d_in[9];
    float* out = (float*)d_out;

    int N = in_sizes[0] / 256;
    int E = in_sizes[1] / 2;

    detect_kernel   <<<1, 256>>>((const int*)ei, E);
    zero_kernel     <<<(N + 255) / 256, 256>>>(N);
    convcount_kernel<<<(E + 255) / 256, 256>>>(ei, E, N);
    scan_kernel     <<<1, 1024>>>(N);
    scatter_kernel  <<<(E + 255) / 256, 256>>>(E, N);

    // layer 1
    cudaFuncSetAttribute(gemm1_kernel, cudaFuncAttributeMaxDynamicSharedMemorySize, 50176);
    gemm1_kernel<<<(N + 127) / 128, 256, 50176>>>(x, W1, atts1, attd1, N);
    agg1_kernel <<<(N + 7) / 8, 256>>>(bias1, N);

    // layer 2
    gemm2_kernel<<<(N + 31) / 32, 256>>>(W2, atts2, attd2, N);
    agg2_kernel <<<(N + 7) / 8, 256>>>(bias2, out, N);
}

// round 5
// speedup vs baseline: 1.9054x; 1.1142x over previous
#include <cuda_runtime.h>
#include <cuda_fp16.h>
#include <math.h>

// Problem constants (fixed by setup_inputs)
#define MAXN 50000
#define MAXE 1600000

typedef unsigned long long ull;

// ---------------- device scratch (globals: allocation-free rule) -----------
__device__ __align__(16) __half2 g_h1h[MAXN * 32]; // layer1 linear out, fp16 [N,64]
__device__ __align__(16) float g_as1[MAXN * 8];
__device__ __align__(16) float g_ad1[MAXN * 8];
__device__ __align__(16) float g_h1p[MAXN * 64];   // layer1 output (post bias+elu)
__device__ __align__(16) __half2 g_h2h[MAXN * 32]; // layer2 linear out, fp16
__device__ __align__(16) float g_as2[MAXN];
__device__ __align__(16) float g_ad2[MAXN];
__device__ int g_srce[MAXE];
__device__ int g_dste[MAXE];
__device__ int g_cnt [MAXN];
__device__ int g_cur [MAXN];
__device__ int g_offs[MAXN + 1];
__device__ int g_bsum[64];
__device__ int g_ebuf[MAXE];
__device__ int g_is64;

// packed f32x2 FMA (sm_103a: only reachable via PTX)
#define FMA_F32X2(d, a, b, c) \
    asm("fma.rn.f32x2 %0, %1, %2, %3;" : "=l"(d) : "l"(a), "l"(b), "l"(c))
#define PACK_DUP_F32X2(d, x) \
    asm("mov.b64 %0, {%1, %1};" : "=l"(d) : "r"(__float_as_uint(x)))
#define UNPACK_F32X2(lo, hi, in) \
    asm("mov.b64 {%0, %1}, %2;" : "=r"(lo), "=r"(hi) : "l"(in))

// ---------------- edge index dtype detect -----------------------------------
__global__ void detect_kernel(const int* __restrict__ ei32, int E) {
    __shared__ int s_or;
    if (threadIdx.x == 0) s_or = 0;
    __syncthreads();
    int acc = 0;
    int nsamp = (E < 4096) ? E : 4096;
    for (int i = threadIdx.x; i < nsamp; i += blockDim.x)
        acc |= ei32[2 * i + 1];
    atomicOr(&s_or, acc);
    __syncthreads();
    if (threadIdx.x == 0) g_is64 = (s_or == 0) ? 1 : 0;
}

__global__ void zero_kernel(int N) {
    int i = blockIdx.x * blockDim.x + threadIdx.x;
    if (i < N) { g_cnt[i] = 0; g_cur[i] = 0; }
}

// fused convert (int64/int32 -> int32 SoA) + count of dst degrees
__global__ void convcount_kernel(const void* __restrict__ ei, int E, int N) {
    int i = blockIdx.x * blockDim.x + threadIdx.x;
    if (i >= E) return;
    int s, d;
    if (g_is64) {
        const long long* e64 = (const long long*)ei;
        s = (int)e64[i];
        d = (int)e64[E + i];
    } else {
        const int* e32 = (const int*)ei;
        s = e32[i];
        d = e32[E + i];
    }
    g_srce[i] = s;
    g_dste[i] = d;
    if ((unsigned)d < (unsigned)N) atomicAdd(&g_cnt[d], 1);
}

// ---------------- multi-block exclusive scan (3 phases) ---------------------
__global__ void scan_block_kernel(int N) {
    __shared__ int wsum[32];
    int tid = threadIdx.x, lane = tid & 31, wid = tid >> 5;
    int i = blockIdx.x * 1024 + tid;
    int v = (i < N) ? g_cnt[i] : 0;
    int sc = v;
    #pragma unroll
    for (int o = 1; o < 32; o <<= 1) {
        int t = __shfl_up_sync(0xffffffffu, sc, o);
        if (lane >= o) sc += t;
    }
    if (lane == 31) wsum[wid] = sc;
    __syncthreads();
    if (wid == 0) {
        int s = wsum[lane];
        #pragma unroll
        for (int o = 1; o < 32; o <<= 1) {
            int t = __shfl_up_sync(0xffffffffu, s, o);
            if (lane >= o) s += t;
        }
        wsum[lane] = s;
    }
    __syncthreads();
    int add = (wid > 0) ? wsum[wid - 1] : 0;
    if (i < N) g_offs[i] = add + sc - v;   // block-local exclusive
    if (tid == 0) g_bsum[blockIdx.x] = wsum[31];
}

__global__ void scan_tops_kernel(int nb, int N) {
    __shared__ int sh[64];
    int tid = threadIdx.x;
    sh[tid] = (tid < nb) ? g_bsum[tid] : 0;
    __syncthreads();
    if (tid == 0) {
        int run = 0;
        for (int j = 0; j < nb; j++) { int t = sh[j]; sh[j] = run; run += t; }
        g_offs[N] = run;
    }
    __syncthreads();
    if (tid < nb) g_bsum[tid] = sh[tid];
}

__global__ void scan_add_kernel(int N) {
    int i = blockIdx.x * 1024 + threadIdx.x;
    if (i < N) g_offs[i] += g_bsum[blockIdx.x];
}

__global__ void scatter_kernel(int E, int N) {
    int i = blockIdx.x * blockDim.x + threadIdx.x;
    if (i < E) {
        int d = g_dste[i];
        if ((unsigned)d < (unsigned)N) {
            int p = atomicAdd(&g_cur[d], 1);
            g_ebuf[g_offs[d] + p] = g_srce[i];
        }
    }
}

// ---------------- layer 1 GEMM: h1 = x @ W1 (f32x2 packed) ------------------
// Tile: 128 rows x 64 cols per block; k chunks of 64.
__global__ void __launch_bounds__(256) gemm1_kernel(
        const float* __restrict__ x, const float* __restrict__ W,
        const float* __restrict__ att_s, const float* __restrict__ att_d,
        int N) {
    extern __shared__ float sm[];
    float* Ws = sm;             // [k][col], 64x64
    float* xs = sm + 64 * 64;   // [row][k], pad 65

    int tid = threadIdx.x;
    int lane = tid & 31;
    int w = tid >> 5;           // warp id = col group = head
    int r0 = blockIdx.x * 128;

    ull acc[16];
    #pragma unroll
    for (int i = 0; i < 16; i++) acc[i] = 0ull;

    for (int kc = 0; kc < 4; kc++) {
        int k0 = kc * 64;
        __syncthreads();
        #pragma unroll
        for (int i = 0; i < 4; i++) {
            int idx = tid + i * 256;
            ((float4*)Ws)[idx] = ((const float4*)W)[(k0 << 4) + idx];
        }
        #pragma unroll
        for (int p = 0; p < 8; p++) {
            int idx = tid + p * 256;
            int row = idx >> 4, f4 = idx & 15;
            int grow = r0 + row;
            float4 v = make_float4(0.f, 0.f, 0.f, 0.f);
            if (grow < N) v = ((const float4*)x)[(size_t)grow * 64 + (k0 >> 2) + f4];
            float* dp = &xs[row * 65 + f4 * 4];
            dp[0] = v.x; dp[1] = v.y; dp[2] = v.z; dp[3] = v.w;
        }
        __syncthreads();

        #pragma unroll 2
        for (int k = 0; k < 64; k++) {
            ull xp[4];
            #pragma unroll
            for (int rr = 0; rr < 4; rr++) {
                float xv = xs[(lane + rr * 32) * 65 + k];
                PACK_DUP_F32X2(xp[rr], xv);
            }
            const ull* wp = (const ull*)&Ws[k * 64 + w * 8];
            ull w0 = wp[0], w1 = wp[1], w2 = wp[2], w3 = wp[3];
            #pragma unroll
            for (int rr = 0; rr < 4; rr++) {
                FMA_F32X2(acc[rr * 4 + 0], xp[rr], w0, acc[rr * 4 + 0]);
                FMA_F32X2(acc[rr * 4 + 1], xp[rr], w1, acc[rr * 4 + 1]);
                FMA_F32X2(acc[rr * 4 + 2], xp[rr], w2, acc[rr * 4 + 2]);
                FMA_F32X2(acc[rr * 4 + 3], xp[rr], w3, acc[rr * 4 + 3]);
            }
        }
    }

    // epilogue: unpack, write h1 (fp16) + attention partials (head == w)
    #pragma unroll
    for (int rr = 0; rr < 4; rr++) {
        int row = r0 + lane + rr * 32;
        if (row >= N) continue;
        float c[8];
        #pragma unroll
        for (int cp = 0; cp < 4; cp++) {
            unsigned lo, hi;
            UNPACK_F32X2(lo, hi, acc[rr * 4 + cp]);
            c[cp * 2]     = __uint_as_float(lo);
            c[cp * 2 + 1] = __uint_as_float(hi);
        }
        __half2 hh[4];
        #pragma unroll
        for (int cp = 0; cp < 4; cp++)
            hh[cp] = __floats2half2_rn(c[cp * 2], c[cp * 2 + 1]);
        *(uint4*)(&g_h1h[(size_t)row * 32 + w * 4]) = *(uint4*)hh;

        float as = 0.f, ad = 0.f;
        #pragma unroll
        for (int j = 0; j < 8; j++) {
            as = fmaf(c[j], att_s[w * 8 + j], as);
            ad = fmaf(c[j], att_d[w * 8 + j], ad);
        }
        g_as1[row * 8 + w] = as;
        g_ad1[row * 8 + w] = ad;
    }
}

// ---------------- layer 1 aggregation: warp per dst, fused softmax+bias+elu
__global__ void agg1_kernel(const float* __restrict__ bias1, int N) {
    int warp = (blockIdx.x * blockDim.x + threadIdx.x) >> 5;
    int lane = threadIdx.x & 31;
    if (warp >= N) return;
    int dst = warp;
    int head = lane >> 2;
    float ad = g_ad1[dst * 8 + head];
    int beg = g_offs[dst], end = g_offs[dst + 1];

    float den = 0.f, ax = 0.f, ay = 0.f;
    #pragma unroll 4
    for (int i = beg; i < end; i++) {
        int s = __ldg(&g_ebuf[i]);
        float e = __ldg(&g_as1[s * 8 + head]) + ad;
        e = (e > 0.f) ? e : 0.2f * e;
        float w = __expf(e);
        float2 hv = __half22float2(g_h1h[(size_t)s * 32 + lane]);
        den += w;
        ax = fmaf(w, hv.x, ax);
        ay = fmaf(w, hv.y, ay);
    }
    float inv = 1.f / (den + 1e-16f);
    int c0 = lane * 2;
    float v0 = fmaf(ax, inv, bias1[c0]);
    float v1 = fmaf(ay, inv, bias1[c0 + 1]);
    v0 = (v0 > 0.f) ? v0 : expm1f(v0);
    v1 = (v1 > 0.f) ? v1 : expm1f(v1);
    ((float2*)g_h1p)[(size_t)dst * 32 + lane] = make_float2(v0, v1);
}

// ---------------- layer 2 GEMM: h2 = h1p @ W2, + a_src2/a_dst2 -------------
__global__ void gemm2_kernel(const float* __restrict__ W2,
                             const float* __restrict__ att_s2, const float* __restrict__ att_d2,
                             int N) {
    __shared__ float Ws[64 * 64];
    __shared__ float xs[32 * 64];
    int tid = threadIdx.x;

    float4* Ws4 = (float4*)Ws;
    const float4* Wg4 = (const float4*)W2;
    #pragma unroll
    for (int i = 0; i < 4; i++) Ws4[tid + i * 256] = Wg4[tid + i * 256];

    int r0 = blockIdx.x * 32;
    float4* xs4 = (float4*)xs;
    const float4* xg4 = (const float4*)(g_h1p + (size_t)r0 * 64);
    int rows = N - r0; if (rows > 32) rows = 32;
    int nf4 = rows * 16;
    #pragma unroll
    for (int i = 0; i < 2; i++) {
        int idx = tid + i * 256;
        xs4[idx] = (idx < nf4) ? xg4[idx] : make_float4(0.f, 0.f, 0.f, 0.f);
    }
    __syncthreads();

    int r = tid >> 3, cg = tid & 7;
    float acc[8];
    #pragma unroll
    for (int j = 0; j < 8; j++) acc[j] = 0.f;
    const float* xr = xs + r * 64;
    #pragma unroll 8
    for (int k = 0; k < 64; k++) {
        float xv = xr[k];
        float4 w0 = Ws4[k * 16 + cg * 2];
        float4 w1 = Ws4[k * 16 + cg * 2 + 1];
        acc[0] = fmaf(xv, w0.x, acc[0]); acc[1] = fmaf(xv, w0.y, acc[1]);
        acc[2] = fmaf(xv, w0.z, acc[2]); acc[3] = fmaf(xv, w0.w, acc[3]);
        acc[4] = fmaf(xv, w1.x, acc[4]); acc[5] = fmaf(xv, w1.y, acc[5]);
        acc[6] = fmaf(xv, w1.z, acc[6]); acc[7] = fmaf(xv, w1.w, acc[7]);
    }

    float ps = 0.f, pd = 0.f;
    #pragma unroll
    for (int j = 0; j < 8; j++) {
        ps = fmaf(acc[j], att_s2[cg * 8 + j], ps);
        pd = fmaf(acc[j], att_d2[cg * 8 + j], pd);
    }
    #pragma unroll
    for (int o = 4; o >= 1; o >>= 1) {
        ps += __shfl_down_sync(0xffffffffu, ps, o);
        pd += __shfl_down_sync(0xffffffffu, pd, o);
    }

    int row = r0 + r;
    if (row < N) {
        __half2 hh[4];
        #pragma unroll
        for (int cp = 0; cp < 4; cp++)
            hh[cp] = __floats2half2_rn(acc[cp * 2], acc[cp * 2 + 1]);
        *(uint4*)(&g_h2h[(size_t)row * 32 + cg * 4]) = *(uint4*)hh;
        if (cg == 0) { g_as2[row] = ps; g_ad2[row] = pd; }
    }
}

// ---------------- layer 2 aggregation + bias + log_softmax -> d_out --------
__global__ void agg2_kernel(const float* __restrict__ bias2, float* __restrict__ out, int N) {
    int warp = (blockIdx.x * blockDim.x + threadIdx.x) >> 5;
    int lane = threadIdx.x & 31;
    if (warp >= N) return;
    int dst = warp;
    float ad = g_ad2[dst];
    int beg = g_offs[dst], end = g_offs[dst + 1];

    float den = 0.f, ax = 0.f, ay = 0.f;
    #pragma unroll 4
    for (int i = beg; i < end; i++) {
        int s = __ldg(&g_ebuf[i]);
        float e = __ldg(&g_as2[s]) + ad;
        e = (e > 0.f) ? e : 0.2f * e;
        float w = __expf(e);
        float2 hv = __half22float2(g_h2h[(size_t)s * 32 + lane]);
        den += w;
        ax = fmaf(w, hv.x, ax);
        ay = fmaf(w, hv.y, ay);
    }
    float inv = 1.f / (den + 1e-16f);
    int c0 = lane * 2;
    float v0 = fmaf(ax, inv, bias2[c0]);
    float v1 = fmaf(ay, inv, bias2[c0 + 1]);

    float m = fmaxf(v0, v1);
    #pragma unroll
    for (int o = 16; o >= 1; o >>= 1) m = fmaxf(m, __shfl_xor_sync(0xffffffffu, m, o));
    float se = __expf(v0 - m) + __expf(v1 - m);
    #pragma unroll
    for (int o = 16; o >= 1; o >>= 1) se += __shfl_xor_sync(0xffffffffu, se, o);
    float lse = m + logf(se);

    ((float2*)out)[(size_t)dst * 32 + lane] = make_float2(v0 - lse, v1 - lse);
}

// ---------------- launch ----------------------------------------------------
extern "C" void kernel_launch(void* const* d_in, const int* in_sizes, int n_in,
                              void* d_out, int out_size) {
    const float* x      = (const float*)d_in[0];
    const void*  ei     = d_in[1];
    const float* W1     = (const float*)d_in[2];
    const float* atts1  = (const float*)d_in[3];
    const float* attd1  = (const float*)d_in[4];
    const float* bias1  = (const float*)d_in[5];
    const float* W2     = (const float*)d_in[6];
    const float* atts2  = (const float*)d_in[7];
    const float* attd2  = (const float*)d_in[8];
    const float* bias2  = (const float*)d_in[9];
    float* out = (float*)d_out;

    int N = in_sizes[0] / 256;
    int E = in_sizes[1] / 2;
    int nb = (N + 1023) / 1024;   // <= 64 for N <= 65536

    detect_kernel   <<<1, 256>>>((const int*)ei, E);
    zero_kernel     <<<(N + 255) / 256, 256>>>(N);
    convcount_kernel<<<(E + 255) / 256, 256>>>(ei, E, N);
    scan_block_kernel<<<nb, 1024>>>(N);
    scan_tops_kernel <<<1, 64>>>(nb, N);
    scan_add_kernel  <<<nb, 1024>>>(N);
    scatter_kernel  <<<(E + 255) / 256, 256>>>(E, N);

    // layer 1
    cudaFuncSetAttribute(gemm1_kernel, cudaFuncAttributeMaxDynamicSharedMemorySize, 50176);
    gemm1_kernel<<<(N + 127) / 128, 256, 50176>>>(x, W1, atts1, attd1, N);
    agg1_kernel <<<(N + 7) / 8, 256>>>(bias1, N);

    // layer 2
    gemm2_kernel<<<(N + 31) / 32, 256>>>(W2, atts2, attd2, N);
    agg2_kernel <<<(N + 7) / 8, 256>>>(bias2, out, N);
}

// round 6
// speedup vs baseline: 1.9169x; 1.0060x over previous
#include <cuda_runtime.h>
#include <cuda_fp16.h>
#include <math.h>

// Problem constants (fixed by setup_inputs)
#define MAXN 50000
#define MAXE 1600000

typedef unsigned long long ull;

// ---------------- device scratch (globals: allocation-free rule) -----------
__device__ __align__(16) __half2 g_h1h[MAXN * 32]; // layer1 linear out, fp16 [N,64]
__device__ __align__(16) float g_as1[MAXN * 8];
__device__ __align__(16) float g_ad1[MAXN * 8];
__device__ __align__(16) float g_h1p[MAXN * 64];   // layer1 output (post bias+elu)
__device__ __align__(16) __half2 g_h2h[MAXN * 32]; // layer2 linear out, fp16
__device__ __align__(16) float g_as2[MAXN];
__device__ __align__(16) float g_ad2[MAXN];
__device__ int g_cnt [MAXN];
__device__ int g_cur [MAXN];
__device__ int g_offs[MAXN + 1];
__device__ int g_bsum[64];
__device__ int g_ebuf[MAXE];
__device__ int g_is64;

// packed f32x2 FMA (sm_103a: only reachable via PTX)
#define FMA_F32X2(d, a, b, c) \
    asm("fma.rn.f32x2 %0, %1, %2, %3;" : "=l"(d) : "l"(a), "l"(b), "l"(c))
#define PACK_DUP_F32X2(d, x) \
    asm("mov.b64 %0, {%1, %1};" : "=l"(d) : "r"(__float_as_uint(x)))
#define UNPACK_F32X2(lo, hi, in) \
    asm("mov.b64 {%0, %1}, %2;" : "=r"(lo), "=r"(hi) : "l"(in))

// ---------------- zero + edge dtype detect (fused) ---------------------------
__global__ void zerodetect_kernel(const int* __restrict__ ei32, int E, int N) {
    int i = blockIdx.x * blockDim.x + threadIdx.x;
    if (i < N) { g_cnt[i] = 0; g_cur[i] = 0; }
    if (blockIdx.x == 0) {
        __shared__ int s_or;
        if (threadIdx.x == 0) s_or = 0;
        __syncthreads();
        int acc = 0;
        int nsamp = (E < 4096) ? E : 4096;
        for (int j = threadIdx.x; j < nsamp; j += blockDim.x)
            acc |= ei32[2 * j + 1];
        atomicOr(&s_or, acc);
        __syncthreads();
        if (threadIdx.x == 0) g_is64 = (s_or == 0) ? 1 : 0;
    }
}

// count dst degrees straight from the raw edge index (dtype branch)
__global__ void count_kernel(const void* __restrict__ ei, int E, int N) {
    int i = blockIdx.x * blockDim.x + threadIdx.x;
    if (i >= E) return;
    int d = g_is64 ? (int)((const long long*)ei)[E + i]
                   : ((const int*)ei)[E + i];
    if ((unsigned)d < (unsigned)N) atomicAdd(&g_cnt[d], 1);
}

// ---------------- multi-block exclusive scan (3 phases) ---------------------
__global__ void scan_block_kernel(int N) {
    __shared__ int wsum[32];
    int tid = threadIdx.x, lane = tid & 31, wid = tid >> 5;
    int i = blockIdx.x * 1024 + tid;
    int v = (i < N) ? g_cnt[i] : 0;
    int sc = v;
    #pragma unroll
    for (int o = 1; o < 32; o <<= 1) {
        int t = __shfl_up_sync(0xffffffffu, sc, o);
        if (lane >= o) sc += t;
    }
    if (lane == 31) wsum[wid] = sc;
    __syncthreads();
    if (wid == 0) {
        int s = wsum[lane];
        #pragma unroll
        for (int o = 1; o < 32; o <<= 1) {
            int t = __shfl_up_sync(0xffffffffu, s, o);
            if (lane >= o) s += t;
        }
        wsum[lane] = s;
    }
    __syncthreads();
    int add = (wid > 0) ? wsum[wid - 1] : 0;
    if (i < N) g_offs[i] = add + sc - v;
    if (tid == 0) g_bsum[blockIdx.x] = wsum[31];
}

__global__ void scan_tops_kernel(int nb, int N) {
    __shared__ int sh[64];
    int tid = threadIdx.x;
    sh[tid] = (tid < nb) ? g_bsum[tid] : 0;
    __syncthreads();
    if (tid == 0) {
        int run = 0;
        for (int j = 0; j < nb; j++) { int t = sh[j]; sh[j] = run; run += t; }
        g_offs[N] = run;
    }
    __syncthreads();
    if (tid < nb) g_bsum[tid] = sh[tid];
}

__global__ void scan_add_kernel(int N) {
    int i = blockIdx.x * 1024 + threadIdx.x;
    if (i < N) g_offs[i] += g_bsum[blockIdx.x];
}

__global__ void scatter_kernel(const void* __restrict__ ei, int E, int N) {
    int i = blockIdx.x * blockDim.x + threadIdx.x;
    if (i >= E) return;
    int s, d;
    if (g_is64) {
        const long long* e64 = (const long long*)ei;
        s = (int)e64[i]; d = (int)e64[E + i];
    } else {
        const int* e32 = (const int*)ei;
        s = e32[i]; d = e32[E + i];
    }
    if ((unsigned)d < (unsigned)N) {
        int p = atomicAdd(&g_cur[d], 1);
        g_ebuf[g_offs[d] + p] = s;
    }
}

// ---------------- layer 1 GEMM: h1 = x @ W1 (f32x2 packed) ------------------
__global__ void __launch_bounds__(256) gemm1_kernel(
        const float* __restrict__ x, const float* __restrict__ W,
        const float* __restrict__ att_s, const float* __restrict__ att_d,
        int N) {
    extern __shared__ float sm[];
    float* Ws = sm;             // [k][col], 64x64
    float* xs = sm + 64 * 64;   // [row][k], pad 65

    int tid = threadIdx.x;
    int lane = tid & 31;
    int w = tid >> 5;           // warp id = col group = head
    int r0 = blockIdx.x * 128;

    ull acc[16];
    #pragma unroll
    for (int i = 0; i < 16; i++) acc[i] = 0ull;

    for (int kc = 0; kc < 4; kc++) {
        int k0 = kc * 64;
        __syncthreads();
        #pragma unroll
        for (int i = 0; i < 4; i++) {
            int idx = tid + i * 256;
            ((float4*)Ws)[idx] = ((const float4*)W)[(k0 << 4) + idx];
        }
        #pragma unroll
        for (int p = 0; p < 8; p++) {
            int idx = tid + p * 256;
            int row = idx >> 4, f4 = idx & 15;
            int grow = r0 + row;
            float4 v = make_float4(0.f, 0.f, 0.f, 0.f);
            if (grow < N) v = ((const float4*)x)[(size_t)grow * 64 + (k0 >> 2) + f4];
            float* dp = &xs[row * 65 + f4 * 4];
            dp[0] = v.x; dp[1] = v.y; dp[2] = v.z; dp[3] = v.w;
        }
        __syncthreads();

        #pragma unroll 2
        for (int k = 0; k < 64; k++) {
            ull xp[4];
            #pragma unroll
            for (int rr = 0; rr < 4; rr++) {
                float xv = xs[(lane + rr * 32) * 65 + k];
                PACK_DUP_F32X2(xp[rr], xv);
            }
            const ull* wp = (const ull*)&Ws[k * 64 + w * 8];
            ull w0 = wp[0], w1 = wp[1], w2 = wp[2], w3 = wp[3];
            #pragma unroll
            for (int rr = 0; rr < 4; rr++) {
                FMA_F32X2(acc[rr * 4 + 0], xp[rr], w0, acc[rr * 4 + 0]);
                FMA_F32X2(acc[rr * 4 + 1], xp[rr], w1, acc[rr * 4 + 1]);
                FMA_F32X2(acc[rr * 4 + 2], xp[rr], w2, acc[rr * 4 + 2]);
                FMA_F32X2(acc[rr * 4 + 3], xp[rr], w3, acc[rr * 4 + 3]);
            }
        }
    }

    #pragma unroll
    for (int rr = 0; rr < 4; rr++) {
        int row = r0 + lane + rr * 32;
        if (row >= N) continue;
        float c[8];
        #pragma unroll
        for (int cp = 0; cp < 4; cp++) {
            unsigned lo, hi;
            UNPACK_F32X2(lo, hi, acc[rr * 4 + cp]);
            c[cp * 2]     = __uint_as_float(lo);
            c[cp * 2 + 1] = __uint_as_float(hi);
        }
        __half2 hh[4];
        #pragma unroll
        for (int cp = 0; cp < 4; cp++)
            hh[cp] = __floats2half2_rn(c[cp * 2], c[cp * 2 + 1]);
        *(uint4*)(&g_h1h[(size_t)row * 32 + w * 4]) = *(uint4*)hh;

        float as = 0.f, ad = 0.f;
        #pragma unroll
        for (int j = 0; j < 8; j++) {
            as = fmaf(c[j], att_s[w * 8 + j], as);
            ad = fmaf(c[j], att_d[w * 8 + j], ad);
        }
        g_as1[row * 8 + w] = as;
        g_ad1[row * 8 + w] = ad;
    }
}

// ---------------- layer 1 aggregation: warp per dst, 4-edge batched ---------
__global__ void agg1_kernel(const float* __restrict__ bias1, int N) {
    int warp = (blockIdx.x * blockDim.x + threadIdx.x) >> 5;
    int lane = threadIdx.x & 31;
    if (warp >= N) return;
    int dst = warp;
    int head = lane >> 2;
    float ad = g_ad1[dst * 8 + head];
    int beg = g_offs[dst], end = g_offs[dst + 1];

    float den = 0.f, ax = 0.f, ay = 0.f;
    int i = beg;
    for (; i + 4 <= end; i += 4) {
        int s0 = __ldg(&g_ebuf[i]);
        int s1 = __ldg(&g_ebuf[i + 1]);
        int s2 = __ldg(&g_ebuf[i + 2]);
        int s3 = __ldg(&g_ebuf[i + 3]);
        float e0 = __ldg(&g_as1[s0 * 8 + head]);
        float e1 = __ldg(&g_as1[s1 * 8 + head]);
        float e2 = __ldg(&g_as1[s2 * 8 + head]);
        float e3 = __ldg(&g_as1[s3 * 8 + head]);
        __half2 q0 = g_h1h[(size_t)s0 * 32 + lane];
        __half2 q1 = g_h1h[(size_t)s1 * 32 + lane];
        __half2 q2 = g_h1h[(size_t)s2 * 32 + lane];
        __half2 q3 = g_h1h[(size_t)s3 * 32 + lane];
        e0 += ad; e1 += ad; e2 += ad; e3 += ad;
        e0 = (e0 > 0.f) ? e0 : 0.2f * e0;
        e1 = (e1 > 0.f) ? e1 : 0.2f * e1;
        e2 = (e2 > 0.f) ? e2 : 0.2f * e2;
        e3 = (e3 > 0.f) ? e3 : 0.2f * e3;
        float w0 = __expf(e0), w1 = __expf(e1), w2 = __expf(e2), w3 = __expf(e3);
        den += (w0 + w1) + (w2 + w3);
        float2 f0 = __half22float2(q0), f1 = __half22float2(q1);
        float2 f2 = __half22float2(q2), f3 = __half22float2(q3);
        ax = fmaf(w0, f0.x, ax); ay = fmaf(w0, f0.y, ay);
        ax = fmaf(w1, f1.x, ax); ay = fmaf(w1, f1.y, ay);
        ax = fmaf(w2, f2.x, ax); ay = fmaf(w2, f2.y, ay);
        ax = fmaf(w3, f3.x, ax); ay = fmaf(w3, f3.y, ay);
    }
    for (; i < end; i++) {
        int s = __ldg(&g_ebuf[i]);
        float e = __ldg(&g_as1[s * 8 + head]) + ad;
        e = (e > 0.f) ? e : 0.2f * e;
        float w = __expf(e);
        float2 hv = __half22float2(g_h1h[(size_t)s * 32 + lane]);
        den += w;
        ax = fmaf(w, hv.x, ax);
        ay = fmaf(w, hv.y, ay);
    }
    float inv = 1.f / (den + 1e-16f);
    int c0 = lane * 2;
    float v0 = fmaf(ax, inv, bias1[c0]);
    float v1 = fmaf(ay, inv, bias1[c0 + 1]);
    v0 = (v0 > 0.f) ? v0 : expm1f(v0);
    v1 = (v1 > 0.f) ? v1 : expm1f(v1);
    ((float2*)g_h1p)[(size_t)dst * 32 + lane] = make_float2(v0, v1);
}

// ---------------- layer 2 GEMM: h2 = h1p @ W2, + a_src2/a_dst2 -------------
__global__ void gemm2_kernel(const float* __restrict__ W2,
                             const float* __restrict__ att_s2, const float* __restrict__ att_d2,
                             int N) {
    __shared__ float Ws[64 * 64];
    __shared__ float xs[32 * 64];
    int tid = threadIdx.x;

    float4* Ws4 = (float4*)Ws;
    const float4* Wg4 = (const float4*)W2;
    #pragma unroll
    for (int i = 0; i < 4; i++) Ws4[tid + i * 256] = Wg4[tid + i * 256];

    int r0 = blockIdx.x * 32;
    float4* xs4 = (float4*)xs;
    const float4* xg4 = (const float4*)(g_h1p + (size_t)r0 * 64);
    int rows = N - r0; if (rows > 32) rows = 32;
    int nf4 = rows * 16;
    #pragma unroll
    for (int i = 0; i < 2; i++) {
        int idx = tid + i * 256;
        xs4[idx] = (idx < nf4) ? xg4[idx] : make_float4(0.f, 0.f, 0.f, 0.f);
    }
    __syncthreads();

    int r = tid >> 3, cg = tid & 7;
    float acc[8];
    #pragma unroll
    for (int j = 0; j < 8; j++) acc[j] = 0.f;
    const float* xr = xs + r * 64;
    #pragma unroll 8
    for (int k = 0; k < 64; k++) {
        float xv = xr[k];
        float4 w0 = Ws4[k * 16 + cg * 2];
        float4 w1 = Ws4[k * 16 + cg * 2 + 1];
        acc[0] = fmaf(xv, w0.x, acc[0]); acc[1] = fmaf(xv, w0.y, acc[1]);
        acc[2] = fmaf(xv, w0.z, acc[2]); acc[3] = fmaf(xv, w0.w, acc[3]);
        acc[4] = fmaf(xv, w1.x, acc[4]); acc[5] = fmaf(xv, w1.y, acc[5]);
        acc[6] = fmaf(xv, w1.z, acc[6]); acc[7] = fmaf(xv, w1.w, acc[7]);
    }

    float ps = 0.f, pd = 0.f;
    #pragma unroll
    for (int j = 0; j < 8; j++) {
        ps = fmaf(acc[j], att_s2[cg * 8 + j], ps);
        pd = fmaf(acc[j], att_d2[cg * 8 + j], pd);
    }
    #pragma unroll
    for (int o = 4; o >= 1; o >>= 1) {
        ps += __shfl_down_sync(0xffffffffu, ps, o);
        pd += __shfl_down_sync(0xffffffffu, pd, o);
    }

    int row = r0 + r;
    if (row < N) {
        __half2 hh[4];
        #pragma unroll
        for (int cp = 0; cp < 4; cp++)
            hh[cp] = __floats2half2_rn(acc[cp * 2], acc[cp * 2 + 1]);
        *(uint4*)(&g_h2h[(size_t)row * 32 + cg * 4]) = *(uint4*)hh;
        if (cg == 0) { g_as2[row] = ps; g_ad2[row] = pd; }
    }
}

// ---------------- layer 2 aggregation + bias + log_softmax -> d_out --------
__global__ void agg2_kernel(const float* __restrict__ bias2, float* __restrict__ out, int N) {
    int warp = (blockIdx.x * blockDim.x + threadIdx.x) >> 5;
    int lane = threadIdx.x & 31;
    if (warp >= N) return;
    int dst = warp;
    float ad = g_ad2[dst];
    int beg = g_offs[dst], end = g_offs[dst + 1];

    float den = 0.f, ax = 0.f, ay = 0.f;
    int i = beg;
    for (; i + 4 <= end; i += 4) {
        int s0 = __ldg(&g_ebuf[i]);
        int s1 = __ldg(&g_ebuf[i + 1]);
        int s2 = __ldg(&g_ebuf[i + 2]);
        int s3 = __ldg(&g_ebuf[i + 3]);
        float e0 = __ldg(&g_as2[s0]);
        float e1 = __ldg(&g_as2[s1]);
        float e2 = __ldg(&g_as2[s2]);
        float e3 = __ldg(&g_as2[s3]);
        __half2 q0 = g_h2h[(size_t)s0 * 32 + lane];
        __half2 q1 = g_h2h[(size_t)s1 * 32 + lane];
        __half2 q2 = g_h2h[(size_t)s2 * 32 + lane];
        __half2 q3 = g_h2h[(size_t)s3 * 32 + lane];
        e0 += ad; e1 += ad; e2 += ad; e3 += ad;
        e0 = (e0 > 0.f) ? e0 : 0.2f * e0;
        e1 = (e1 > 0.f) ? e1 : 0.2f * e1;
        e2 = (e2 > 0.f) ? e2 : 0.2f * e2;
        e3 = (e3 > 0.f) ? e3 : 0.2f * e3;
        float w0 = __expf(e0), w1 = __expf(e1), w2 = __expf(e2), w3 = __expf(e3);
        den += (w0 + w1) + (w2 + w3);
        float2 f0 = __half22float2(q0), f1 = __half22float2(q1);
        float2 f2 = __half22float2(q2), f3 = __half22float2(q3);
        ax = fmaf(w0, f0.x, ax); ay = fmaf(w0, f0.y, ay);
        ax = fmaf(w1, f1.x, ax); ay = fmaf(w1, f1.y, ay);
        ax = fmaf(w2, f2.x, ax); ay = fmaf(w2, f2.y, ay);
        ax = fmaf(w3, f3.x, ax); ay = fmaf(w3, f3.y, ay);
    }
    for (; i < end; i++) {
        int s = __ldg(&g_ebuf[i]);
        float e = __ldg(&g_as2[s]) + ad;
        e = (e > 0.f) ? e : 0.2f * e;
        float w = __expf(e);
        float2 hv = __half22float2(g_h2h[(size_t)s * 32 + lane]);
        den += w;
        ax = fmaf(w, hv.x, ax);
        ay = fmaf(w, hv.y, ay);
    }
    float inv = 1.f / (den + 1e-16f);
    int c0 = lane * 2;
    float v0 = fmaf(ax, inv, bias2[c0]);
    float v1 = fmaf(ay, inv, bias2[c0 + 1]);

    float m = fmaxf(v0, v1);
    #pragma unroll
    for (int o = 16; o >= 1; o >>= 1) m = fmaxf(m, __shfl_xor_sync(0xffffffffu, m, o));
    float se = __expf(v0 - m) + __expf(v1 - m);
    #pragma unroll
    for (int o = 16; o >= 1; o >>= 1) se += __shfl_xor_sync(0xffffffffu, se, o);
    float lse = m + logf(se);

    ((float2*)out)[(size_t)dst * 32 + lane] = make_float2(v0 - lse, v1 - lse);
}

// ---------------- launch ----------------------------------------------------
extern "C" void kernel_launch(void* const* d_in, const int* in_sizes, int n_in,
                              void* d_out, int out_size) {
    const float* x      = (const float*)d_in[0];
    const void*  ei     = d_in[1];
    const float* W1     = (const float*)d_in[2];
    const float* atts1  = (const float*)d_in[3];
    const float* attd1  = (const float*)d_in[4];
    const float* bias1  = (const float*)d_in[5];
    const float* W2     = (const float*)d_in[6];
    const float* atts2  = (const float*)d_in[7];
    const float* attd2  = (const float*)d_in[8];
    const float* bias2  = (const float*)d_in[9];
    float* out = (float*)d_out;

    int N = in_sizes[0] / 256;
    int E = in_sizes[1] / 2;
    int nb = (N + 1023) / 1024;

    zerodetect_kernel<<<(N + 255) / 256, 256>>>((const int*)ei, E, N);
    count_kernel     <<<(E + 255) / 256, 256>>>(ei, E, N);
    scan_block_kernel<<<nb, 1024>>>(N);
    // gemm1 placed here (CSR-independent) so the launch-index-3 ncu capture
    // profiles it next round.
    cudaFuncSetAttribute(gemm1_kernel, cudaFuncAttributeMaxDynamicSharedMemorySize, 50176);
    gemm1_kernel<<<(N + 127) / 128, 256, 50176>>>(x, W1, atts1, attd1, N);
    scan_tops_kernel <<<1, 64>>>(nb, N);
    scan_add_kernel  <<<nb, 1024>>>(N);
    scatter_kernel   <<<(E + 255) / 256, 256>>>(ei, E, N);

    agg1_kernel <<<(N + 7) / 8, 256>>>(bias1, N);
    gemm2_kernel<<<(N + 31) / 32, 256>>>(W2, atts2, attd2, N);
    agg2_kernel <<<(N + 7) / 8, 256>>>(bias2, out, N);
}

// round 8
// speedup vs baseline: 1.9357x; 1.0098x over previous
#include <cuda_runtime.h>
#include <cuda_fp16.h>
#include <mma.h>
#include <math.h>
#include <cstdint>

#define MAXN 50000
#define MAXE 1600000

using namespace nvcuda;

// ---------------- device scratch ------------------------------------------
__device__ __align__(16) __half2 g_h1h[MAXN * 32]; // layer1 h, fp16 [N,64]
__device__ __align__(16) float g_as1[MAXN * 8];
__device__ __align__(16) float g_ad1[MAXN * 8];
__device__ __align__(16) float g_h1p[MAXN * 64];   // layer1 out (bias+elu)
__device__ __align__(16) __half2 g_h2h[MAXN * 32]; // layer2 h, fp16
__device__ __align__(16) float g_as2[MAXN];
__device__ __align__(16) float g_ad2[MAXN];
__device__ __align__(16) __half g_wh[256 * 64];    // W1 fp16 [256][64] (row-major)
__device__ int g_cnt [MAXN];
__device__ int g_cur [MAXN];
__device__ int g_offs[MAXN + 1];
__device__ int g_bsum[64];
__device__ __align__(16) int g_ebuf[MAXE];
__device__ int g_is64;

// ---------------- zero + edge dtype detect ---------------------------------
__global__ void zerodetect_kernel(const int* __restrict__ ei32, int E, int N) {
    int i = blockIdx.x * blockDim.x + threadIdx.x;
    if (i < N) { g_cnt[i] = 0; g_cur[i] = 0; }
    if (blockIdx.x == 0) {
        __shared__ int s_or;
        if (threadIdx.x == 0) s_or = 0;
        __syncthreads();
        int acc = 0;
        int nsamp = (E < 4096) ? E : 4096;
        for (int j = threadIdx.x; j < nsamp; j += blockDim.x)
            acc |= ei32[2 * j + 1];
        atomicOr(&s_or, acc);
        __syncthreads();
        if (threadIdx.x == 0) g_is64 = (s_or == 0) ? 1 : 0;
    }
}

// ---------------- W1 -> fp16 (same [256][64] layout) ------------------------
__global__ void wconv_kernel(const float* __restrict__ W1) {
    int i = blockIdx.x * blockDim.x + threadIdx.x;   // 16384
    g_wh[i] = __float2half_rn(W1[i]);
}

__global__ void count_kernel(const void* __restrict__ ei, int E, int N) {
    int i = blockIdx.x * blockDim.x + threadIdx.x;
    if (i >= E) return;
    int d = g_is64 ? (int)((const long long*)ei)[E + i]
                   : ((const int*)ei)[E + i];
    if ((unsigned)d < (unsigned)N) atomicAdd(&g_cnt[d], 1);
}

// ---------------- layer 1 GEMM via WMMA fp16 (HMMA) -------------------------
// Block: 128 rows x 64 cols, 256 threads (8 warps, 1 warp per 16-row stripe).
// smem: W fp16 [256][64] 32KB + scratch region (x chunks fp16 / out floats).
#define XS_LD 72   // half elements per row (pad: 144B stride)
#define OS_LD 72   // float elements per row
__global__ void __launch_bounds__(256) gemm1_wmma_kernel(
        const float* __restrict__ x,
        const float* __restrict__ att_s, const float* __restrict__ att_d,
        int N) {
    extern __shared__ char smem[];
    __half* Wsm = (__half*)smem;                   // [256][64] = 32KB
    __half* xs  = (__half*)(smem + 32768);         // [128][XS_LD] = 18KB
    float*  osm = (float*)(smem + 32768);          // [128][OS_LD] = 36.8KB (aliases xs)

    int tid = threadIdx.x;
    int wid = tid >> 5;
    int r0 = blockIdx.x * 128;

    // load W fp16 once: 2048 uint4
    #pragma unroll
    for (int i = 0; i < 8; i++)
        ((uint4*)Wsm)[tid + i * 256] = ((const uint4*)g_wh)[tid + i * 256];

    wmma::fragment<wmma::accumulator, 16, 16, 16, float> c[4];
    #pragma unroll
    for (int n = 0; n < 4; n++) wmma::fill_fragment(c[n], 0.f);

    for (int kc = 0; kc < 4; kc++) {
        __syncthreads();
        // x chunk: rows r0..r0+127, k = kc*64..+63, fp32 -> fp16 smem
        #pragma unroll
        for (int it = 0; it < 8; it++) {
            int idx = tid + it * 256;      // 0..2047 float4 chunks
            int row = idx >> 4, f4 = idx & 15;
            int grow = r0 + row;
            float4 v = make_float4(0.f, 0.f, 0.f, 0.f);
            if (grow < N) v = ((const float4*)x)[(size_t)grow * 64 + (kc << 4) + f4];
            __half2 h01 = __floats2half2_rn(v.x, v.y);
            __half2 h23 = __floats2half2_rn(v.z, v.w);
            *(uint2*)&xs[row * XS_LD + f4 * 4] =
                make_uint2(*(uint32_t*)&h01, *(uint32_t*)&h23);
        }
        __syncthreads();

        #pragma unroll
        for (int k16 = 0; k16 < 4; k16++) {
            wmma::fragment<wmma::matrix_a, 16, 16, 16, __half, wmma::row_major> a;
            wmma::load_matrix_sync(a, &xs[wid * 16 * XS_LD + k16 * 16], XS_LD);
            #pragma unroll
            for (int n = 0; n < 4; n++) {
                wmma::fragment<wmma::matrix_b, 16, 16, 16, __half, wmma::row_major> b;
                wmma::load_matrix_sync(b, &Wsm[(kc * 64 + k16 * 16) * 64 + n * 16], 64);
                wmma::mma_sync(c[n], a, b, c[n]);
            }
        }
    }

    __syncthreads();   // xs dead; osm takes over the region
    #pragma unroll
    for (int n = 0; n < 4; n++)
        wmma::store_matrix_sync(&osm[wid * 16 * OS_LD + n * 16], c[n], OS_LD,
                                wmma::mem_row_major);
    __syncthreads();

    // epilogue: 2 threads per row; each handles 32 cols = 4 heads
    int row = tid >> 1, half = tid & 1;
    int grow = r0 + row;
    if (grow < N) {
        const float* orow = &osm[row * OS_LD + half * 32];
        // h1 fp16: 32 cols = 16 half2 = 4 uint4
        #pragma unroll
        for (int q = 0; q < 4; q++) {
            __half2 hh[4];
            #pragma unroll
            for (int p = 0; p < 4; p++)
                hh[p] = __floats2half2_rn(orow[q * 8 + p * 2], orow[q * 8 + p * 2 + 1]);
            *(uint4*)(&g_h1h[(size_t)grow * 32 + half * 16 + q * 4]) = *(uint4*)hh;
        }
        // attention partials: heads half*4 .. half*4+3
        #pragma unroll
        for (int hh = 0; hh < 4; hh++) {
            int h = half * 4 + hh;
            float as = 0.f, ad = 0.f;
            #pragma unroll
            for (int j = 0; j < 8; j++) {
                float cv = orow[hh * 8 + j];
                as = fmaf(cv, __ldg(&att_s[h * 8 + j]), as);
                ad = fmaf(cv, __ldg(&att_d[h * 8 + j]), ad);
            }
            g_as1[grow * 8 + h] = as;
            g_ad1[grow * 8 + h] = ad;
        }
    }
}

// ---------------- scan (block phase) ----------------------------------------
__global__ void scan_block_kernel(int N) {
    __shared__ int wsum[32];
    int tid = threadIdx.x, lane = tid & 31, wid = tid >> 5;
    int i = blockIdx.x * 1024 + tid;
    int v = (i < N) ? g_cnt[i] : 0;
    int sc = v;
    #pragma unroll
    for (int o = 1; o < 32; o <<= 1) {
        int t = __shfl_up_sync(0xffffffffu, sc, o);
        if (lane >= o) sc += t;
    }
    if (lane == 31) wsum[wid] = sc;
    __syncthreads();
    if (wid == 0) {
        int s = wsum[lane];
        #pragma unroll
        for (int o = 1; o < 32; o <<= 1) {
            int t = __shfl_up_sync(0xffffffffu, s, o);
            if (lane >= o) s += t;
        }
        wsum[lane] = s;
    }
    __syncthreads();
    int add = (wid > 0) ? wsum[wid - 1] : 0;
    if (i < N) g_offs[i] = add + sc - v;
    if (tid == 0) g_bsum[blockIdx.x] = wsum[31];
}

// fused: each block computes its own bsum prefix, adds, last block writes total
__global__ void scan_add_kernel(int N, int nb) {
    __shared__ int prefix;
    int b = blockIdx.x;
    int lane = threadIdx.x & 31;
    if (threadIdx.x < 32) {
        int acc = 0;
        for (int j = lane; j < b; j += 32) acc += g_bsum[j];
        #pragma unroll
        for (int o = 16; o >= 1; o >>= 1) acc += __shfl_xor_sync(0xffffffffu, acc, o);
        if (lane == 0) prefix = acc;
    }
    __syncthreads();
    int i = b * 1024 + threadIdx.x;
    if (i < N) g_offs[i] += prefix;
    if (b == nb - 1 && threadIdx.x == 0) g_offs[N] = prefix + g_bsum[b];
}

__global__ void scatter_kernel(const void* __restrict__ ei, int E, int N) {
    int i = blockIdx.x * blockDim.x + threadIdx.x;
    if (i >= E) return;
    int s, d;
    if (g_is64) {
        const long long* e64 = (const long long*)ei;
        s = (int)e64[i]; d = (int)e64[E + i];
    } else {
        const int* e32 = (const int*)ei;
        s = e32[i]; d = e32[E + i];
    }
    if ((unsigned)d < (unsigned)N) {
        int p = atomicAdd(&g_cur[d], 1);
        g_ebuf[g_offs[d] + p] = s;
    }
}

// ---------------- layer 1 aggregation ---------------------------------------
__global__ void agg1_kernel(const float* __restrict__ bias1, int N) {
    int warp = (blockIdx.x * blockDim.x + threadIdx.x) >> 5;
    int lane = threadIdx.x & 31;
    if (warp >= N) return;
    int dst = warp;
    int head = lane >> 2;
    float ad = g_ad1[dst * 8 + head];
    int beg = g_offs[dst], end = g_offs[dst + 1];

    float den = 0.f, ax = 0.f, ay = 0.f;
    int i = beg;
    for (; i < end && (i & 3); i++) {
        int s = __ldg(&g_ebuf[i]);
        float e = __ldg(&g_as1[s * 8 + head]) + ad;
        e = (e > 0.f) ? e : 0.2f * e;
        float w = __expf(e);
        float2 hv = __half22float2(g_h1h[(size_t)s * 32 + lane]);
        den += w; ax = fmaf(w, hv.x, ax); ay = fmaf(w, hv.y, ay);
    }
    for (; i + 4 <= end; i += 4) {
        int4 ss = *(const int4*)&g_ebuf[i];      // 1 broadcast LDG.128
        float e0 = __ldg(&g_as1[ss.x * 8 + head]);
        float e1 = __ldg(&g_as1[ss.y * 8 + head]);
        float e2 = __ldg(&g_as1[ss.z * 8 + head]);
        float e3 = __ldg(&g_as1[ss.w * 8 + head]);
        __half2 q0 = g_h1h[(size_t)ss.x * 32 + lane];
        __half2 q1 = g_h1h[(size_t)ss.y * 32 + lane];
        __half2 q2 = g_h1h[(size_t)ss.z * 32 + lane];
        __half2 q3 = g_h1h[(size_t)ss.w * 32 + lane];
        e0 += ad; e1 += ad; e2 += ad; e3 += ad;
        e0 = (e0 > 0.f) ? e0 : 0.2f * e0;
        e1 = (e1 > 0.f) ? e1 : 0.2f * e1;
        e2 = (e2 > 0.f) ? e2 : 0.2f * e2;
        e3 = (e3 > 0.f) ? e3 : 0.2f * e3;
        float w0 = __expf(e0), w1 = __expf(e1), w2 = __expf(e2), w3 = __expf(e3);
        den += (w0 + w1) + (w2 + w3);
        float2 f0 = __half22float2(q0), f1 = __half22float2(q1);
        float2 f2 = __half22float2(q2), f3 = __half22float2(q3);
        ax = fmaf(w0, f0.x, ax); ay = fmaf(w0, f0.y, ay);
        ax = fmaf(w1, f1.x, ax); ay = fmaf(w1, f1.y, ay);
        ax = fmaf(w2, f2.x, ax); ay = fmaf(w2, f2.y, ay);
        ax = fmaf(w3, f3.x, ax); ay = fmaf(w3, f3.y, ay);
    }
    for (; i < end; i++) {
        int s = __ldg(&g_ebuf[i]);
        float e = __ldg(&g_as1[s * 8 + head]) + ad;
        e = (e > 0.f) ? e : 0.2f * e;
        float w = __expf(e);
        float2 hv = __half22float2(g_h1h[(size_t)s * 32 + lane]);
        den += w; ax = fmaf(w, hv.x, ax); ay = fmaf(w, hv.y, ay);
    }
    float inv = 1.f / (den + 1e-16f);
    int c0 = lane * 2;
    float v0 = fmaf(ax, inv, bias1[c0]);
    float v1 = fmaf(ay, inv, bias1[c0 + 1]);
    v0 = (v0 > 0.f) ? v0 : expm1f(v0);
    v1 = (v1 > 0.f) ? v1 : expm1f(v1);
    ((float2*)g_h1p)[(size_t)dst * 32 + lane] = make_float2(v0, v1);
}

// ---------------- layer 2 GEMM ----------------------------------------------
__global__ void gemm2_kernel(const float* __restrict__ W2,
                             const float* __restrict__ att_s2, const float* __restrict__ att_d2,
                             int N) {
    __shared__ float Ws[64 * 64];
    __shared__ float xs[32 * 64];
    int tid = threadIdx.x;

    float4* Ws4 = (float4*)Ws;
    const float4* Wg4 = (const float4*)W2;
    #pragma unroll
    for (int i = 0; i < 4; i++) Ws4[tid + i * 256] = Wg4[tid + i * 256];

    int r0 = blockIdx.x * 32;
    float4* xs4 = (float4*)xs;
    const float4* xg4 = (const float4*)(g_h1p + (size_t)r0 * 64);
    int rows = N - r0; if (rows > 32) rows = 32;
    int nf4 = rows * 16;
    #pragma unroll
    for (int i = 0; i < 2; i++) {
        int idx = tid + i * 256;
        xs4[idx] = (idx < nf4) ? xg4[idx] : make_float4(0.f, 0.f, 0.f, 0.f);
    }
    __syncthreads();

    int r = tid >> 3, cg = tid & 7;
    float acc[8];
    #pragma unroll
    for (int j = 0; j < 8; j++) acc[j] = 0.f;
    const float* xr = xs + r * 64;
    #pragma unroll 8
    for (int k = 0; k < 64; k++) {
        float xv = xr[k];
        float4 w0 = Ws4[k * 16 + cg * 2];
        float4 w1 = Ws4[k * 16 + cg * 2 + 1];
        acc[0] = fmaf(xv, w0.x, acc[0]); acc[1] = fmaf(xv, w0.y, acc[1]);
        acc[2] = fmaf(xv, w0.z, acc[2]); acc[3] = fmaf(xv, w0.w, acc[3]);
        acc[4] = fmaf(xv, w1.x, acc[4]); acc[5] = fmaf(xv, w1.y, acc[5]);
        acc[6] = fmaf(xv, w1.z, acc[6]); acc[7] = fmaf(xv, w1.w, acc[7]);
    }

    float ps = 0.f, pd = 0.f;
    #pragma unroll
    for (int j = 0; j < 8; j++) {
        ps = fmaf(acc[j], att_s2[cg * 8 + j], ps);
        pd = fmaf(acc[j], att_d2[cg * 8 + j], pd);
    }
    #pragma unroll
    for (int o = 4; o >= 1; o >>= 1) {
        ps += __shfl_down_sync(0xffffffffu, ps, o);
        pd += __shfl_down_sync(0xffffffffu, pd, o);
    }

    int row = r0 + r;
    if (row < N) {
        __half2 hh[4];
        #pragma unroll
        for (int cp = 0; cp < 4; cp++)
            hh[cp] = __floats2half2_rn(acc[cp * 2], acc[cp * 2 + 1]);
        *(uint4*)(&g_h2h[(size_t)row * 32 + cg * 4]) = *(uint4*)hh;
        if (cg == 0) { g_as2[row] = ps; g_ad2[row] = pd; }
    }
}

// ---------------- layer 2 aggregation + log_softmax -------------------------
__global__ void agg2_kernel(const float* __restrict__ bias2, float* __restrict__ out, int N) {
    int warp = (blockIdx.x * blockDim.x + threadIdx.x) >> 5;
    int lane = threadIdx.x & 31;
    if (warp >= N) return;
    int dst = warp;
    float ad = g_ad2[dst];
    int beg = g_offs[dst], end = g_offs[dst + 1];

    float den = 0.f, ax = 0.f, ay = 0.f;
    int i = beg;
    for (; i < end && (i & 3); i++) {
        int s = __ldg(&g_ebuf[i]);
        float e = __ldg(&g_as2[s]) + ad;
        e = (e > 0.f) ? e : 0.2f * e;
        float w = __expf(e);
        float2 hv = __half22float2(g_h2h[(size_t)s * 32 + lane]);
        den += w; ax = fmaf(w, hv.x, ax); ay = fmaf(w, hv.y, ay);
    }
    for (; i + 4 <= end; i += 4) {
        int4 ss = *(const int4*)&g_ebuf[i];
        float e0 = __ldg(&g_as2[ss.x]);
        float e1 = __ldg(&g_as2[ss.y]);
        float e2 = __ldg(&g_as2[ss.z]);
        float e3 = __ldg(&g_as2[ss.w]);
        __half2 q0 = g_h2h[(size_t)ss.x * 32 + lane];
        __half2 q1 = g_h2h[(size_t)ss.y * 32 + lane];
        __half2 q2 = g_h2h[(size_t)ss.z * 32 + lane];
        __half2 q3 = g_h2h[(size_t)ss.w * 32 + lane];
        e0 += ad; e1 += ad; e2 += ad; e3 += ad;
        e0 = (e0 > 0.f) ? e0 : 0.2f * e0;
        e1 = (e1 > 0.f) ? e1 : 0.2f * e1;
        e2 = (e2 > 0.f) ? e2 : 0.2f * e2;
        e3 = (e3 > 0.f) ? e3 : 0.2f * e3;
        float w0 = __expf(e0), w1 = __expf(e1), w2 = __expf(e2), w3 = __expf(e3);
        den += (w0 + w1) + (w2 + w3);
        float2 f0 = __half22float2(q0), f1 = __half22float2(q1);
        float2 f2 = __half22float2(q2), f3 = __half22float2(q3);
        ax = fmaf(w0, f0.x, ax); ay = fmaf(w0, f0.y, ay);
        ax = fmaf(w1, f1.x, ax); ay = fmaf(w1, f1.y, ay);
        ax = fmaf(w2, f2.x, ax); ay = fmaf(w2, f2.y, ay);
        ax = fmaf(w3, f3.x, ax); ay = fmaf(w3, f3.y, ay);
    }
    for (; i < end; i++) {
        int s = __ldg(&g_ebuf[i]);
        float e = __ldg(&g_as2[s]) + ad;
        e = (e > 0.f) ? e : 0.2f * e;
        float w = __expf(e);
        float2 hv = __half22float2(g_h2h[(size_t)s * 32 + lane]);
        den += w; ax = fmaf(w, hv.x, ax); ay = fmaf(w, hv.y, ay);
    }
    float inv = 1.f / (den + 1e-16f);
    int c0 = lane * 2;
    float v0 = fmaf(ax, inv, bias2[c0]);
    float v1 = fmaf(ay, inv, bias2[c0 + 1]);

    float m = fmaxf(v0, v1);
    #pragma unroll
    for (int o = 16; o >= 1; o >>= 1) m = fmaxf(m, __shfl_xor_sync(0xffffffffu, m, o));
    float se = __expf(v0 - m) + __expf(v1 - m);
    #pragma unroll
    for (int o = 16; o >= 1; o >>= 1) se += __shfl_xor_sync(0xffffffffu, se, o);
    float lse = m + logf(se);

    ((float2*)out)[(size_t)dst * 32 + lane] = make_float2(v0 - lse, v1 - lse);
}

// ---------------- launch ----------------------------------------------------
extern "C" void kernel_launch(void* const* d_in, const int* in_sizes, int n_in,
                              void* d_out, int out_size) {
    const float* x      = (const float*)d_in[0];
    const void*  ei     = d_in[1];
    const float* W1     = (const float*)d_in[2];
    const float* atts1  = (const float*)d_in[3];
    const float* attd1  = (const float*)d_in[4];
    const float* bias1  = (const float*)d_in[5];
    const float* W2     = (const float*)d_in[6];
    const float* atts2  = (const float*)d_in[7];
    const float* attd2  = (const float*)d_in[8];
    const float* bias2  = (const float*)d_in[9];
    float* out = (float*)d_out;

    int N = in_sizes[0] / 256;
    int E = in_sizes[1] / 2;
    int nb = (N + 1023) / 1024;

    zerodetect_kernel<<<(N + 255) / 256, 256>>>((const int*)ei, E, N);
    wconv_kernel     <<<64, 256>>>(W1);
    count_kernel     <<<(E + 255) / 256, 256>>>(ei, E, N);

    // profiled slot (launch index 3): WMMA gemm1
    cudaFuncSetAttribute(gemm1_wmma_kernel, cudaFuncAttributeMaxDynamicSharedMemorySize, 69632);
    gemm1_wmma_kernel<<<(N + 127) / 128, 256, 69632>>>(x, atts1, attd1, N);

    scan_block_kernel<<<nb, 1024>>>(N);
    scan_add_kernel  <<<nb, 1024>>>(N, nb);
    scatter_kernel   <<<(E + 255) / 256, 256>>>(ei, E, N);

    agg1_kernel <<<(N + 7) / 8, 256>>>(bias1, N);
    gemm2_kernel<<<(N + 31) / 32, 256>>>(W2, atts2, attd2, N);
    agg2_kernel <<<(N + 7) / 8, 256>>>(bias2, out, N);
}

// round 9
// speedup vs baseline: 2.1645x; 1.1182x over previous
#include <cuda_runtime.h>
#include <cuda_fp16.h>
#include <mma.h>
#include <math.h>
#include <cstdint>

#define MAXN 50000
#define MAXE 1600000

using namespace nvcuda;

// ---------------- device scratch ------------------------------------------
__device__ __align__(16) __half2 g_h1h[MAXN * 32]; // layer1 h, fp16 [N,64]
__device__ __align__(16) float g_as1[MAXN * 8];
__device__ __align__(16) float g_ad1[MAXN * 8];
__device__ __align__(16) float g_h1p[MAXN * 64];   // layer1 out (bias+elu)
__device__ __align__(16) __half2 g_h2h[MAXN * 32]; // layer2 h, fp16
__device__ __align__(16) float g_as2[MAXN];
__device__ __align__(16) float g_ad2[MAXN];
__device__ __align__(16) __half g_wh[256 * 64];    // W1 fp16 [256][64] (row-major)
__device__ int g_cnt [MAXN];
__device__ int g_cur [MAXN];
__device__ int g_offs[MAXN + 1];
__device__ int g_bsum[64];
__device__ __align__(16) int g_ebuf[MAXE];
__device__ int g_is64;

// ---------------- zero + edge dtype detect ---------------------------------
__global__ void zerodetect_kernel(const int* __restrict__ ei32, int E, int N) {
    int i = blockIdx.x * blockDim.x + threadIdx.x;
    if (i < N) { g_cnt[i] = 0; g_cur[i] = 0; }
    if (blockIdx.x == 0) {
        __shared__ int s_or;
        if (threadIdx.x == 0) s_or = 0;
        __syncthreads();
        int acc = 0;
        int nsamp = (E < 4096) ? E : 4096;
        for (int j = threadIdx.x; j < nsamp; j += blockDim.x)
            acc |= ei32[2 * j + 1];
        atomicOr(&s_or, acc);
        __syncthreads();
        if (threadIdx.x == 0) g_is64 = (s_or == 0) ? 1 : 0;
    }
}

// ---------------- W1 -> fp16 (same [256][64] layout) ------------------------
__global__ void wconv_kernel(const float* __restrict__ W1) {
    int i = blockIdx.x * blockDim.x + threadIdx.x;   // 16384
    g_wh[i] = __float2half_rn(W1[i]);
}

__global__ void count_kernel(const void* __restrict__ ei, int E, int N) {
    int i = blockIdx.x * blockDim.x + threadIdx.x;
    if (i >= E) return;
    int d = g_is64 ? (int)((const long long*)ei)[E + i]
                   : ((const int*)ei)[E + i];
    if ((unsigned)d < (unsigned)N) atomicAdd(&g_cnt[d], 1);
}

// ---------------- layer 1 GEMM via WMMA fp16 (HMMA) -------------------------
// Block: 128 rows x 64 cols, 256 threads (8 warps, 1 warp per 16-row stripe).
// Single-phase: whole x tile + whole W loaded up front (full MLP), then 16
// uninterrupted WMMA k-steps. All smem strides are odd multiples of 16B ->
// conflict-free ldmatrix.
#define WS_LD 72    // half elems per W row  (144B stride)
#define XS_LD 264   // half elems per x row  (528B stride)
#define OS_LD 72    // float elems per out row
__global__ void __launch_bounds__(256) gemm1_wmma_kernel(
        const float* __restrict__ x,
        const float* __restrict__ att_s, const float* __restrict__ att_d,
        int N) {
    extern __shared__ char smem[];
    __half* Wsm = (__half*)smem;                     // [256][WS_LD] = 36864B
    __half* xs  = (__half*)(smem + 36864);           // [128][XS_LD] = 67584B
    float*  osm = (float*)(smem + 36864);            // [128][OS_LD] aliases xs

    int tid = threadIdx.x;
    int wid = tid >> 5;
    int r0 = blockIdx.x * 128;

    // W: 2048 uint4 into padded rows
    #pragma unroll
    for (int i = 0; i < 8; i++) {
        int idx = tid + i * 256;          // 0..2047
        int row = idx >> 3, q = idx & 7;
        *(uint4*)&Wsm[row * WS_LD + q * 8] = ((const uint4*)g_wh)[idx];
    }
    // x: whole tile, 8192 float4 -> fp16, 32 independent LDG.128 per thread
    #pragma unroll
    for (int it = 0; it < 32; it++) {
        int idx = tid + it * 256;         // 0..8191
        int row = idx >> 6, f4 = idx & 63;
        int grow = r0 + row;
        float4 v = make_float4(0.f, 0.f, 0.f, 0.f);
        if (grow < N) v = ((const float4*)x)[(size_t)grow * 64 + f4];
        __half2 h01 = __floats2half2_rn(v.x, v.y);
        __half2 h23 = __floats2half2_rn(v.z, v.w);
        *(uint2*)&xs[row * XS_LD + f4 * 4] =
            make_uint2(*(uint32_t*)&h01, *(uint32_t*)&h23);
    }
    __syncthreads();

    wmma::fragment<wmma::accumulator, 16, 16, 16, float> c[4];
    #pragma unroll
    for (int n = 0; n < 4; n++) wmma::fill_fragment(c[n], 0.f);

    #pragma unroll
    for (int k16 = 0; k16 < 16; k16++) {
        wmma::fragment<wmma::matrix_a, 16, 16, 16, __half, wmma::row_major> a;
        wmma::load_matrix_sync(a, &xs[wid * 16 * XS_LD + k16 * 16], XS_LD);
        #pragma unroll
        for (int n = 0; n < 4; n++) {
            wmma::fragment<wmma::matrix_b, 16, 16, 16, __half, wmma::row_major> b;
            wmma::load_matrix_sync(b, &Wsm[k16 * 16 * WS_LD + n * 16], WS_LD);
            wmma::mma_sync(c[n], a, b, c[n]);
        }
    }

    __syncthreads();   // xs dead; osm takes over the region
    #pragma unroll
    for (int n = 0; n < 4; n++)
        wmma::store_matrix_sync(&osm[wid * 16 * OS_LD + n * 16], c[n], OS_LD,
                                wmma::mem_row_major);
    __syncthreads();

    // epilogue: 2 threads per row; each handles 32 cols = 4 heads
    int row = tid >> 1, half = tid & 1;
    int grow = r0 + row;
    if (grow < N) {
        const float* orow = &osm[row * OS_LD + half * 32];
        #pragma unroll
        for (int q = 0; q < 4; q++) {
            __half2 hh[4];
            #pragma unroll
            for (int p = 0; p < 4; p++)
                hh[p] = __floats2half2_rn(orow[q * 8 + p * 2], orow[q * 8 + p * 2 + 1]);
            *(uint4*)(&g_h1h[(size_t)grow * 32 + half * 16 + q * 4]) = *(uint4*)hh;
        }
        #pragma unroll
        for (int hh = 0; hh < 4; hh++) {
            int h = half * 4 + hh;
            float as = 0.f, ad = 0.f;
            #pragma unroll
            for (int j = 0; j < 8; j++) {
                float cv = orow[hh * 8 + j];
                as = fmaf(cv, __ldg(&att_s[h * 8 + j]), as);
                ad = fmaf(cv, __ldg(&att_d[h * 8 + j]), ad);
            }
            g_as1[grow * 8 + h] = as;
            g_ad1[grow * 8 + h] = ad;
        }
    }
}

// ---------------- scan (block phase) ----------------------------------------
__global__ void scan_block_kernel(int N) {
    __shared__ int wsum[32];
    int tid = threadIdx.x, lane = tid & 31, wid = tid >> 5;
    int i = blockIdx.x * 1024 + tid;
    int v = (i < N) ? g_cnt[i] : 0;
    int sc = v;
    #pragma unroll
    for (int o = 1; o < 32; o <<= 1) {
        int t = __shfl_up_sync(0xffffffffu, sc, o);
        if (lane >= o) sc += t;
    }
    if (lane == 31) wsum[wid] = sc;
    __syncthreads();
    if (wid == 0) {
        int s = wsum[lane];
        #pragma unroll
        for (int o = 1; o < 32; o <<= 1) {
            int t = __shfl_up_sync(0xffffffffu, s, o);
            if (lane >= o) s += t;
        }
        wsum[lane] = s;
    }
    __syncthreads();
    int add = (wid > 0) ? wsum[wid - 1] : 0;
    if (i < N) g_offs[i] = add + sc - v;
    if (tid == 0) g_bsum[blockIdx.x] = wsum[31];
}

__global__ void scan_add_kernel(int N, int nb) {
    __shared__ int prefix;
    int b = blockIdx.x;
    int lane = threadIdx.x & 31;
    if (threadIdx.x < 32) {
        int acc = 0;
        for (int j = lane; j < b; j += 32) acc += g_bsum[j];
        #pragma unroll
        for (int o = 16; o >= 1; o >>= 1) acc += __shfl_xor_sync(0xffffffffu, acc, o);
        if (lane == 0) prefix = acc;
    }
    __syncthreads();
    int i = b * 1024 + threadIdx.x;
    if (i < N) g_offs[i] += prefix;
    if (b == nb - 1 && threadIdx.x == 0) g_offs[N] = prefix + g_bsum[b];
}

__global__ void scatter_kernel(const void* __restrict__ ei, int E, int N) {
    int i = blockIdx.x * blockDim.x + threadIdx.x;
    if (i >= E) return;
    int s, d;
    if (g_is64) {
        const long long* e64 = (const long long*)ei;
        s = (int)e64[i]; d = (int)e64[E + i];
    } else {
        const int* e32 = (const int*)ei;
        s = e32[i]; d = e32[E + i];
    }
    if ((unsigned)d < (unsigned)N) {
        int p = atomicAdd(&g_cur[d], 1);
        g_ebuf[g_offs[d] + p] = s;
    }
}

// ---------------- layer 1 aggregation ---------------------------------------
__global__ void agg1_kernel(const float* __restrict__ bias1, int N) {
    int warp = (blockIdx.x * blockDim.x + threadIdx.x) >> 5;
    int lane = threadIdx.x & 31;
    if (warp >= N) return;
    int dst = warp;
    int head = lane >> 2;
    float ad = g_ad1[dst * 8 + head];
    int beg = g_offs[dst], end = g_offs[dst + 1];

    float den = 0.f, ax = 0.f, ay = 0.f;
    int i = beg;
    for (; i < end && (i & 3); i++) {
        int s = __ldg(&g_ebuf[i]);
        float e = __ldg(&g_as1[s * 8 + head]) + ad;
        e = (e > 0.f) ? e : 0.2f * e;
        float w = __expf(e);
        float2 hv = __half22float2(g_h1h[(size_t)s * 32 + lane]);
        den += w; ax = fmaf(w, hv.x, ax); ay = fmaf(w, hv.y, ay);
    }
    for (; i + 4 <= end; i += 4) {
        int4 ss = *(const int4*)&g_ebuf[i];
        float e0 = __ldg(&g_as1[ss.x * 8 + head]);
        float e1 = __ldg(&g_as1[ss.y * 8 + head]);
        float e2 = __ldg(&g_as1[ss.z * 8 + head]);
        float e3 = __ldg(&g_as1[ss.w * 8 + head]);
        __half2 q0 = g_h1h[(size_t)ss.x * 32 + lane];
        __half2 q1 = g_h1h[(size_t)ss.y * 32 + lane];
        __half2 q2 = g_h1h[(size_t)ss.z * 32 + lane];
        __half2 q3 = g_h1h[(size_t)ss.w * 32 + lane];
        e0 += ad; e1 += ad; e2 += ad; e3 += ad;
        e0 = (e0 > 0.f) ? e0 : 0.2f * e0;
        e1 = (e1 > 0.f) ? e1 : 0.2f * e1;
        e2 = (e2 > 0.f) ? e2 : 0.2f * e2;
        e3 = (e3 > 0.f) ? e3 : 0.2f * e3;
        float w0 = __expf(e0), w1 = __expf(e1), w2 = __expf(e2), w3 = __expf(e3);
        den += (w0 + w1) + (w2 + w3);
        float2 f0 = __half22float2(q0), f1 = __half22float2(q1);
        float2 f2 = __half22float2(q2), f3 = __half22float2(q3);
        ax = fmaf(w0, f0.x, ax); ay = fmaf(w0, f0.y, ay);
        ax = fmaf(w1, f1.x, ax); ay = fmaf(w1, f1.y, ay);
        ax = fmaf(w2, f2.x, ax); ay = fmaf(w2, f2.y, ay);
        ax = fmaf(w3, f3.x, ax); ay = fmaf(w3, f3.y, ay);
    }
    for (; i < end; i++) {
        int s = __ldg(&g_ebuf[i]);
        float e = __ldg(&g_as1[s * 8 + head]) + ad;
        e = (e > 0.f) ? e : 0.2f * e;
        float w = __expf(e);
        float2 hv = __half22float2(g_h1h[(size_t)s * 32 + lane]);
        den += w; ax = fmaf(w, hv.x, ax); ay = fmaf(w, hv.y, ay);
    }
    float inv = 1.f / (den + 1e-16f);
    int c0 = lane * 2;
    float v0 = fmaf(ax, inv, bias1[c0]);
    float v1 = fmaf(ay, inv, bias1[c0 + 1]);
    v0 = (v0 > 0.f) ? v0 : expm1f(v0);
    v1 = (v1 > 0.f) ? v1 : expm1f(v1);
    ((float2*)g_h1p)[(size_t)dst * 32 + lane] = make_float2(v0, v1);
}

// ---------------- layer 2 GEMM ----------------------------------------------
__global__ void gemm2_kernel(const float* __restrict__ W2,
                             const float* __restrict__ att_s2, const float* __restrict__ att_d2,
                             int N) {
    __shared__ float Ws[64 * 64];
    __shared__ float xs[32 * 64];
    int tid = threadIdx.x;

    float4* Ws4 = (float4*)Ws;
    const float4* Wg4 = (const float4*)W2;
    #pragma unroll
    for (int i = 0; i < 4; i++) Ws4[tid + i * 256] = Wg4[tid + i * 256];

    int r0 = blockIdx.x * 32;
    float4* xs4 = (float4*)xs;
    const float4* xg4 = (const float4*)(g_h1p + (size_t)r0 * 64);
    int rows = N - r0; if (rows > 32) rows = 32;
    int nf4 = rows * 16;
    #pragma unroll
    for (int i = 0; i < 2; i++) {
        int idx = tid + i * 256;
        xs4[idx] = (idx < nf4) ? xg4[idx] : make_float4(0.f, 0.f, 0.f, 0.f);
    }
    __syncthreads();

    int r = tid >> 3, cg = tid & 7;
    float acc[8];
    #pragma unroll
    for (int j = 0; j < 8; j++) acc[j] = 0.f;
    const float* xr = xs + r * 64;
    #pragma unroll 8
    for (int k = 0; k < 64; k++) {
        float xv = xr[k];
        float4 w0 = Ws4[k * 16 + cg * 2];
        float4 w1 = Ws4[k * 16 + cg * 2 + 1];
        acc[0] = fmaf(xv, w0.x, acc[0]); acc[1] = fmaf(xv, w0.y, acc[1]);
        acc[2] = fmaf(xv, w0.z, acc[2]); acc[3] = fmaf(xv, w0.w, acc[3]);
        acc[4] = fmaf(xv, w1.x, acc[4]); acc[5] = fmaf(xv, w1.y, acc[5]);
        acc[6] = fmaf(xv, w1.z, acc[6]); acc[7] = fmaf(xv, w1.w, acc[7]);
    }

    float ps = 0.f, pd = 0.f;
    #pragma unroll
    for (int j = 0; j < 8; j++) {
        ps = fmaf(acc[j], att_s2[cg * 8 + j], ps);
        pd = fmaf(acc[j], att_d2[cg * 8 + j], pd);
    }
    #pragma unroll
    for (int o = 4; o >= 1; o >>= 1) {
        ps += __shfl_down_sync(0xffffffffu, ps, o);
        pd += __shfl_down_sync(0xffffffffu, pd, o);
    }

    int row = r0 + r;
    if (row < N) {
        __half2 hh[4];
        #pragma unroll
        for (int cp = 0; cp < 4; cp++)
            hh[cp] = __floats2half2_rn(acc[cp * 2], acc[cp * 2 + 1]);
        *(uint4*)(&g_h2h[(size_t)row * 32 + cg * 4]) = *(uint4*)hh;
        if (cg == 0) { g_as2[row] = ps; g_ad2[row] = pd; }
    }
}

// ---------------- layer 2 aggregation + log_softmax -------------------------
__global__ void agg2_kernel(const float* __restrict__ bias2, float* __restrict__ out, int N) {
    int warp = (blockIdx.x * blockDim.x + threadIdx.x) >> 5;
    int lane = threadIdx.x & 31;
    if (warp >= N) return;
    int dst = warp;
    float ad = g_ad2[dst];
    int beg = g_offs[dst], end = g_offs[dst + 1];

    float den = 0.f, ax = 0.f, ay = 0.f;
    int i = beg;
    for (; i < end && (i & 3); i++) {
        int s = __ldg(&g_ebuf[i]);
        float e = __ldg(&g_as2[s]) + ad;
        e = (e > 0.f) ? e : 0.2f * e;
        float w = __expf(e);
        float2 hv = __half22float2(g_h2h[(size_t)s * 32 + lane]);
        den += w; ax = fmaf(w, hv.x, ax); ay = fmaf(w, hv.y, ay);
    }
    for (; i + 4 <= end; i += 4) {
        int4 ss = *(const int4*)&g_ebuf[i];
        float e0 = __ldg(&g_as2[ss.x]);
        float e1 = __ldg(&g_as2[ss.y]);
        float e2 = __ldg(&g_as2[ss.z]);
        float e3 = __ldg(&g_as2[ss.w]);
        __half2 q0 = g_h2h[(size_t)ss.x * 32 + lane];
        __half2 q1 = g_h2h[(size_t)ss.y * 32 + lane];
        __half2 q2 = g_h2h[(size_t)ss.z * 32 + lane];
        __half2 q3 = g_h2h[(size_t)ss.w * 32 + lane];
        e0 += ad; e1 += ad; e2 += ad; e3 += ad;
        e0 = (e0 > 0.f) ? e0 : 0.2f * e0;
        e1 = (e1 > 0.f) ? e1 : 0.2f * e1;
        e2 = (e2 > 0.f) ? e2 : 0.2f * e2;
        e3 = (e3 > 0.f) ? e3 : 0.2f * e3;
        float w0 = __expf(e0), w1 = __expf(e1), w2 = __expf(e2), w3 = __expf(e3);
        den += (w0 + w1) + (w2 + w3);
        float2 f0 = __half22float2(q0), f1 = __half22float2(q1);
        float2 f2 = __half22float2(q2), f3 = __half22float2(q3);
        ax = fmaf(w0, f0.x, ax); ay = fmaf(w0, f0.y, ay);
        ax = fmaf(w1, f1.x, ax); ay = fmaf(w1, f1.y, ay);
        ax = fmaf(w2, f2.x, ax); ay = fmaf(w2, f2.y, ay);
        ax = fmaf(w3, f3.x, ax); ay = fmaf(w3, f3.y, ay);
    }
    for (; i < end; i++) {
        int s = __ldg(&g_ebuf[i]);
        float e = __ldg(&g_as2[s]) + ad;
        e = (e > 0.f) ? e : 0.2f * e;
        float w = __expf(e);
        float2 hv = __half22float2(g_h2h[(size_t)s * 32 + lane]);
        den += w; ax = fmaf(w, hv.x, ax); ay = fmaf(w, hv.y, ay);
    }
    float inv = 1.f / (den + 1e-16f);
    int c0 = lane * 2;
    float v0 = fmaf(ax, inv, bias2[c0]);
    float v1 = fmaf(ay, inv, bias2[c0 + 1]);

    float m = fmaxf(v0, v1);
    #pragma unroll
    for (int o = 16; o >= 1; o >>= 1) m = fmaxf(m, __shfl_xor_sync(0xffffffffu, m, o));
    float se = __expf(v0 - m) + __expf(v1 - m);
    #pragma unroll
    for (int o = 16; o >= 1; o >>= 1) se += __shfl_xor_sync(0xffffffffu, se, o);
    float lse = m + logf(se);

    ((float2*)out)[(size_t)dst * 32 + lane] = make_float2(v0 - lse, v1 - lse);
}

// ---------------- launch ----------------------------------------------------
extern "C" void kernel_launch(void* const* d_in, const int* in_sizes, int n_in,
                              void* d_out, int out_size) {
    const float* x      = (const float*)d_in[0];
    const void*  ei     = d_in[1];
    const float* W1     = (const float*)d_in[2];
    const float* atts1  = (const float*)d_in[3];
    const float* attd1  = (const float*)d_in[4];
    const float* bias1  = (const float*)d_in[5];
    const float* W2     = (const float*)d_in[6];
    const float* atts2  = (const float*)d_in[7];
    const float* attd2  = (const float*)d_in[8];
    const float* bias2  = (const float*)d_in[9];
    float* out = (float*)d_out;

    int N = in_sizes[0] / 256;
    int E = in_sizes[1] / 2;
    int nb = (N + 1023) / 1024;

    zerodetect_kernel<<<(N + 255) / 256, 256>>>((const int*)ei, E, N);
    wconv_kernel     <<<64, 256>>>(W1);
    count_kernel     <<<(E + 255) / 256, 256>>>(ei, E, N);

    // profiled slot (launch index 3): WMMA gemm1 (single-phase, padded smem)
    cudaFuncSetAttribute(gemm1_wmma_kernel, cudaFuncAttributeMaxDynamicSharedMemorySize, 104448);
    gemm1_wmma_kernel<<<(N + 127) / 128, 256, 104448>>>(x, atts1, attd1, N);

    scan_block_kernel<<<nb, 1024>>>(N);
    scan_add_kernel  <<<nb, 1024>>>(N, nb);
    scatter_kernel   <<<(E + 255) / 256, 256>>>(ei, E, N);

    agg1_kernel <<<(N + 7) / 8, 256>>>(bias1, N);
    gemm2_kernel<<<(N + 31) / 32, 256>>>(W2, atts2, attd2, N);
    agg2_kernel <<<(N + 7) / 8, 256>>>(bias2, out, N);
}

// round 10
// speedup vs baseline: 2.2399x; 1.0348x over previous
#include <cuda_runtime.h>
#include <cuda_fp16.h>
#include <mma.h>
#include <math.h>
#include <cstdint>

#define MAXN 50000
#define MAXE 1600000

using namespace nvcuda;

// ---------------- device scratch ------------------------------------------
__device__ __align__(16) __half2 g_h1h[MAXN * 32]; // layer1 h, fp16 [N,64]
__device__ __align__(16) float g_as1[MAXN * 8];
__device__ __align__(16) float g_ad1[MAXN * 8];
__device__ __align__(16) float g_h1p[MAXN * 64];   // layer1 out (bias+elu)
__device__ __align__(16) __half2 g_h2h[MAXN * 32]; // layer2 h, fp16
__device__ __align__(16) float g_as2[MAXN];
__device__ __align__(16) float g_ad2[MAXN];
__device__ __align__(16) __half g_wh[256 * 64];    // W1 fp16 [256][64]
__device__ int g_cnt [MAXN];
__device__ int g_cur [MAXN];
__device__ int g_offs[MAXN + 1];
__device__ int g_bsum[64];
__device__ __align__(16) int g_ebuf[MAXE];
__device__ int g_is64;

// ---------------- zero + edge dtype detect ---------------------------------
__global__ void zerodetect_kernel(const int* __restrict__ ei32, int E, int N) {
    int i = blockIdx.x * blockDim.x + threadIdx.x;
    if (i < N) { g_cnt[i] = 0; g_cur[i] = 0; }
    if (blockIdx.x == 0) {
        __shared__ int s_or;
        if (threadIdx.x == 0) s_or = 0;
        __syncthreads();
        int acc = 0;
        int nsamp = (E < 4096) ? E : 4096;
        for (int j = threadIdx.x; j < nsamp; j += blockDim.x)
            acc |= ei32[2 * j + 1];
        atomicOr(&s_or, acc);
        __syncthreads();
        if (threadIdx.x == 0) g_is64 = (s_or == 0) ? 1 : 0;
    }
}

// ---------------- W1 -> fp16 -------------------------------------------------
__global__ void wconv_kernel(const float* __restrict__ W1) {
    int i = blockIdx.x * blockDim.x + threadIdx.x;   // 16384
    g_wh[i] = __float2half_rn(W1[i]);
}

__global__ void count_kernel(const void* __restrict__ ei, int E, int N) {
    int i = blockIdx.x * blockDim.x + threadIdx.x;
    if (i >= E) return;
    int d = g_is64 ? (int)((const long long*)ei)[E + i]
                   : ((const int*)ei)[E + i];
    if ((unsigned)d < (unsigned)N) atomicAdd(&g_cnt[d], 1);
}

// ---------------- layer 1 GEMM via WMMA fp16 (HMMA) -------------------------
#define WS_LD 72
#define XS_LD 264
#define OS_LD 72
__global__ void __launch_bounds__(256) gemm1_wmma_kernel(
        const float* __restrict__ x,
        const float* __restrict__ att_s, const float* __restrict__ att_d,
        int N) {
    extern __shared__ char smem[];
    __half* Wsm = (__half*)smem;                     // [256][WS_LD]
    __half* xs  = (__half*)(smem + 36864);           // [128][XS_LD]
    float*  osm = (float*)(smem + 36864);            // aliases xs

    int tid = threadIdx.x;
    int wid = tid >> 5;
    int r0 = blockIdx.x * 128;

    #pragma unroll
    for (int i = 0; i < 8; i++) {
        int idx = tid + i * 256;
        int row = idx >> 3, q = idx & 7;
        *(uint4*)&Wsm[row * WS_LD + q * 8] = ((const uint4*)g_wh)[idx];
    }
    #pragma unroll
    for (int it = 0; it < 32; it++) {
        int idx = tid + it * 256;
        int row = idx >> 6, f4 = idx & 63;
        int grow = r0 + row;
        float4 v = make_float4(0.f, 0.f, 0.f, 0.f);
        if (grow < N) v = ((const float4*)x)[(size_t)grow * 64 + f4];
        __half2 h01 = __floats2half2_rn(v.x, v.y);
        __half2 h23 = __floats2half2_rn(v.z, v.w);
        *(uint2*)&xs[row * XS_LD + f4 * 4] =
            make_uint2(*(uint32_t*)&h01, *(uint32_t*)&h23);
    }
    __syncthreads();

    wmma::fragment<wmma::accumulator, 16, 16, 16, float> c[4];
    #pragma unroll
    for (int n = 0; n < 4; n++) wmma::fill_fragment(c[n], 0.f);

    #pragma unroll
    for (int k16 = 0; k16 < 16; k16++) {
        wmma::fragment<wmma::matrix_a, 16, 16, 16, __half, wmma::row_major> a;
        wmma::load_matrix_sync(a, &xs[wid * 16 * XS_LD + k16 * 16], XS_LD);
        #pragma unroll
        for (int n = 0; n < 4; n++) {
            wmma::fragment<wmma::matrix_b, 16, 16, 16, __half, wmma::row_major> b;
            wmma::load_matrix_sync(b, &Wsm[k16 * 16 * WS_LD + n * 16], WS_LD);
            wmma::mma_sync(c[n], a, b, c[n]);
        }
    }

    __syncthreads();
    #pragma unroll
    for (int n = 0; n < 4; n++)
        wmma::store_matrix_sync(&osm[wid * 16 * OS_LD + n * 16], c[n], OS_LD,
                                wmma::mem_row_major);
    __syncthreads();

    int row = tid >> 1, half = tid & 1;
    int grow = r0 + row;
    if (grow < N) {
        const float* orow = &osm[row * OS_LD + half * 32];
        #pragma unroll
        for (int q = 0; q < 4; q++) {
            __half2 hh[4];
            #pragma unroll
            for (int p = 0; p < 4; p++)
                hh[p] = __floats2half2_rn(orow[q * 8 + p * 2], orow[q * 8 + p * 2 + 1]);
            *(uint4*)(&g_h1h[(size_t)grow * 32 + half * 16 + q * 4]) = *(uint4*)hh;
        }
        #pragma unroll
        for (int hh = 0; hh < 4; hh++) {
            int h = half * 4 + hh;
            float as = 0.f, ad = 0.f;
            #pragma unroll
            for (int j = 0; j < 8; j++) {
                float cv = orow[hh * 8 + j];
                as = fmaf(cv, __ldg(&att_s[h * 8 + j]), as);
                ad = fmaf(cv, __ldg(&att_d[h * 8 + j]), ad);
            }
            g_as1[grow * 8 + h] = as;
            g_ad1[grow * 8 + h] = ad;
        }
    }
}

// ---------------- scan ------------------------------------------------------
__global__ void scan_block_kernel(int N) {
    __shared__ int wsum[32];
    int tid = threadIdx.x, lane = tid & 31, wid = tid >> 5;
    int i = blockIdx.x * 1024 + tid;
    int v = (i < N) ? g_cnt[i] : 0;
    int sc = v;
    #pragma unroll
    for (int o = 1; o < 32; o <<= 1) {
        int t = __shfl_up_sync(0xffffffffu, sc, o);
        if (lane >= o) sc += t;
    }
    if (lane == 31) wsum[wid] = sc;
    __syncthreads();
    if (wid == 0) {
        int s = wsum[lane];
        #pragma unroll
        for (int o = 1; o < 32; o <<= 1) {
            int t = __shfl_up_sync(0xffffffffu, s, o);
            if (lane >= o) s += t;
        }
        wsum[lane] = s;
    }
    __syncthreads();
    int add = (wid > 0) ? wsum[wid - 1] : 0;
    if (i < N) g_offs[i] = add + sc - v;
    if (tid == 0) g_bsum[blockIdx.x] = wsum[31];
}

__global__ void scan_add_kernel(int N, int nb) {
    __shared__ int prefix;
    int b = blockIdx.x;
    int lane = threadIdx.x & 31;
    if (threadIdx.x < 32) {
        int acc = 0;
        for (int j = lane; j < b; j += 32) acc += g_bsum[j];
        #pragma unroll
        for (int o = 16; o >= 1; o >>= 1) acc += __shfl_xor_sync(0xffffffffu, acc, o);
        if (lane == 0) prefix = acc;
    }
    __syncthreads();
    int i = b * 1024 + threadIdx.x;
    if (i < N) g_offs[i] += prefix;
    if (b == nb - 1 && threadIdx.x == 0) g_offs[N] = prefix + g_bsum[b];
}

__global__ void scatter_kernel(const void* __restrict__ ei, int E, int N) {
    int i = blockIdx.x * blockDim.x + threadIdx.x;
    if (i >= E) return;
    int s, d;
    if (g_is64) {
        const long long* e64 = (const long long*)ei;
        s = (int)e64[i]; d = (int)e64[E + i];
    } else {
        const int* e32 = (const int*)ei;
        s = e32[i]; d = e32[E + i];
    }
    if ((unsigned)d < (unsigned)N) {
        int p = atomicAdd(&g_cur[d], 1);
        g_ebuf[g_offs[d] + p] = s;
    }
}

// ---------------- agg helpers ------------------------------------------------
#define LRELU(e) ((e) > 0.f ? (e) : 0.2f * (e))

// ---------------- layer 1 aggregation ---------------------------------------
__global__ void agg1_kernel(const float* __restrict__ bias1, int N) {
    int warp = (blockIdx.x * blockDim.x + threadIdx.x) >> 5;
    int lane = threadIdx.x & 31;
    if (warp >= N) return;
    int dst = warp;
    int head = lane >> 2;
    float ad = g_ad1[dst * 8 + head];
    int beg = g_offs[dst], end = g_offs[dst + 1];

    float den = 0.f, ax = 0.f, ay = 0.f;
    int i = beg;
    for (; i < end && (i & 3); i++) {
        int s = __ldg(&g_ebuf[i]);
        float e = LRELU(__ldg(&g_as1[s * 8 + head]) + ad);
        float w = __expf(e);
        float2 hv = __half22float2(__ldg(&g_h1h[(size_t)s * 32 + lane]));
        den += w; ax = fmaf(w, hv.x, ax); ay = fmaf(w, hv.y, ay);
    }
    // 8-edge batches: two LDG.128 + 8 independent e-loads + 8 h-gathers
    for (; i + 8 <= end; i += 8) {
        int4 sa = *(const int4*)&g_ebuf[i];
        int4 sb = *(const int4*)&g_ebuf[i + 4];
        float e0 = __ldg(&g_as1[sa.x * 8 + head]);
        float e1 = __ldg(&g_as1[sa.y * 8 + head]);
        float e2 = __ldg(&g_as1[sa.z * 8 + head]);
        float e3 = __ldg(&g_as1[sa.w * 8 + head]);
        float e4 = __ldg(&g_as1[sb.x * 8 + head]);
        float e5 = __ldg(&g_as1[sb.y * 8 + head]);
        float e6 = __ldg(&g_as1[sb.z * 8 + head]);
        float e7 = __ldg(&g_as1[sb.w * 8 + head]);
        __half2 q0 = __ldg(&g_h1h[(size_t)sa.x * 32 + lane]);
        __half2 q1 = __ldg(&g_h1h[(size_t)sa.y * 32 + lane]);
        __half2 q2 = __ldg(&g_h1h[(size_t)sa.z * 32 + lane]);
        __half2 q3 = __ldg(&g_h1h[(size_t)sa.w * 32 + lane]);
        __half2 q4 = __ldg(&g_h1h[(size_t)sb.x * 32 + lane]);
        __half2 q5 = __ldg(&g_h1h[(size_t)sb.y * 32 + lane]);
        __half2 q6 = __ldg(&g_h1h[(size_t)sb.z * 32 + lane]);
        __half2 q7 = __ldg(&g_h1h[(size_t)sb.w * 32 + lane]);
        float w0 = __expf(LRELU(e0 + ad)), w1 = __expf(LRELU(e1 + ad));
        float w2 = __expf(LRELU(e2 + ad)), w3 = __expf(LRELU(e3 + ad));
        float w4 = __expf(LRELU(e4 + ad)), w5 = __expf(LRELU(e5 + ad));
        float w6 = __expf(LRELU(e6 + ad)), w7 = __expf(LRELU(e7 + ad));
        den += ((w0 + w1) + (w2 + w3)) + ((w4 + w5) + (w6 + w7));
        float2 f0 = __half22float2(q0), f1 = __half22float2(q1);
        float2 f2 = __half22float2(q2), f3 = __half22float2(q3);
        float2 f4 = __half22float2(q4), f5 = __half22float2(q5);
        float2 f6 = __half22float2(q6), f7 = __half22float2(q7);
        ax = fmaf(w0, f0.x, ax); ay = fmaf(w0, f0.y, ay);
        ax = fmaf(w1, f1.x, ax); ay = fmaf(w1, f1.y, ay);
        ax = fmaf(w2, f2.x, ax); ay = fmaf(w2, f2.y, ay);
        ax = fmaf(w3, f3.x, ax); ay = fmaf(w3, f3.y, ay);
        ax = fmaf(w4, f4.x, ax); ay = fmaf(w4, f4.y, ay);
        ax = fmaf(w5, f5.x, ax); ay = fmaf(w5, f5.y, ay);
        ax = fmaf(w6, f6.x, ax); ay = fmaf(w6, f6.y, ay);
        ax = fmaf(w7, f7.x, ax); ay = fmaf(w7, f7.y, ay);
    }
    for (; i + 4 <= end; i += 4) {
        int4 ss = *(const int4*)&g_ebuf[i];
        float e0 = __ldg(&g_as1[ss.x * 8 + head]);
        float e1 = __ldg(&g_as1[ss.y * 8 + head]);
        float e2 = __ldg(&g_as1[ss.z * 8 + head]);
        float e3 = __ldg(&g_as1[ss.w * 8 + head]);
        __half2 q0 = __ldg(&g_h1h[(size_t)ss.x * 32 + lane]);
        __half2 q1 = __ldg(&g_h1h[(size_t)ss.y * 32 + lane]);
        __half2 q2 = __ldg(&g_h1h[(size_t)ss.z * 32 + lane]);
        __half2 q3 = __ldg(&g_h1h[(size_t)ss.w * 32 + lane]);
        float w0 = __expf(LRELU(e0 + ad)), w1 = __expf(LRELU(e1 + ad));
        float w2 = __expf(LRELU(e2 + ad)), w3 = __expf(LRELU(e3 + ad));
        den += (w0 + w1) + (w2 + w3);
        float2 f0 = __half22float2(q0), f1 = __half22float2(q1);
        float2 f2 = __half22float2(q2), f3 = __half22float2(q3);
        ax = fmaf(w0, f0.x, ax); ay = fmaf(w0, f0.y, ay);
        ax = fmaf(w1, f1.x, ax); ay = fmaf(w1, f1.y, ay);
        ax = fmaf(w2, f2.x, ax); ay = fmaf(w2, f2.y, ay);
        ax = fmaf(w3, f3.x, ax); ay = fmaf(w3, f3.y, ay);
    }
    for (; i < end; i++) {
        int s = __ldg(&g_ebuf[i]);
        float e = LRELU(__ldg(&g_as1[s * 8 + head]) + ad);
        float w = __expf(e);
        float2 hv = __half22float2(__ldg(&g_h1h[(size_t)s * 32 + lane]));
        den += w; ax = fmaf(w, hv.x, ax); ay = fmaf(w, hv.y, ay);
    }
    float inv = 1.f / (den + 1e-16f);
    int c0 = lane * 2;
    float v0 = fmaf(ax, inv, bias1[c0]);
    float v1 = fmaf(ay, inv, bias1[c0 + 1]);
    v0 = (v0 > 0.f) ? v0 : expm1f(v0);
    v1 = (v1 > 0.f) ? v1 : expm1f(v1);
    ((float2*)g_h1p)[(size_t)dst * 32 + lane] = make_float2(v0, v1);
}

// ---------------- layer 2 GEMM ----------------------------------------------
__global__ void gemm2_kernel(const float* __restrict__ W2,
                             const float* __restrict__ att_s2, const float* __restrict__ att_d2,
                             int N) {
    __shared__ float Ws[64 * 64];
    __shared__ float xs[32 * 64];
    int tid = threadIdx.x;

    float4* Ws4 = (float4*)Ws;
    const float4* Wg4 = (const float4*)W2;
    #pragma unroll
    for (int i = 0; i < 4; i++) Ws4[tid + i * 256] = Wg4[tid + i * 256];

    int r0 = blockIdx.x * 32;
    float4* xs4 = (float4*)xs;
    const float4* xg4 = (const float4*)(g_h1p + (size_t)r0 * 64);
    int rows = N - r0; if (rows > 32) rows = 32;
    int nf4 = rows * 16;
    #pragma unroll
    for (int i = 0; i < 2; i++) {
        int idx = tid + i * 256;
        xs4[idx] = (idx < nf4) ? xg4[idx] : make_float4(0.f, 0.f, 0.f, 0.f);
    }
    __syncthreads();

    int r = tid >> 3, cg = tid & 7;
    float acc[8];
    #pragma unroll
    for (int j = 0; j < 8; j++) acc[j] = 0.f;
    const float* xr = xs + r * 64;
    #pragma unroll 8
    for (int k = 0; k < 64; k++) {
        float xv = xr[k];
        float4 w0 = Ws4[k * 16 + cg * 2];
        float4 w1 = Ws4[k * 16 + cg * 2 + 1];
        acc[0] = fmaf(xv, w0.x, acc[0]); acc[1] = fmaf(xv, w0.y, acc[1]);
        acc[2] = fmaf(xv, w0.z, acc[2]); acc[3] = fmaf(xv, w0.w, acc[3]);
        acc[4] = fmaf(xv, w1.x, acc[4]); acc[5] = fmaf(xv, w1.y, acc[5]);
        acc[6] = fmaf(xv, w1.z, acc[6]); acc[7] = fmaf(xv, w1.w, acc[7]);
    }

    float ps = 0.f, pd = 0.f;
    #pragma unroll
    for (int j = 0; j < 8; j++) {
        ps = fmaf(acc[j], att_s2[cg * 8 + j], ps);
        pd = fmaf(acc[j], att_d2[cg * 8 + j], pd);
    }
    #pragma unroll
    for (int o = 4; o >= 1; o >>= 1) {
        ps += __shfl_down_sync(0xffffffffu, ps, o);
        pd += __shfl_down_sync(0xffffffffu, pd, o);
    }

    int row = r0 + r;
    if (row < N) {
        __half2 hh[4];
        #pragma unroll
        for (int cp = 0; cp < 4; cp++)
            hh[cp] = __floats2half2_rn(acc[cp * 2], acc[cp * 2 + 1]);
        *(uint4*)(&g_h2h[(size_t)row * 32 + cg * 4]) = *(uint4*)hh;
        if (cg == 0) { g_as2[row] = ps; g_ad2[row] = pd; }
    }
}

// ---------------- layer 2 aggregation + log_softmax -------------------------
__global__ void agg2_kernel(const float* __restrict__ bias2, float* __restrict__ out, int N) {
    int warp = (blockIdx.x * blockDim.x + threadIdx.x) >> 5;
    int lane = threadIdx.x & 31;
    if (warp >= N) return;
    int dst = warp;
    float ad = g_ad2[dst];
    int beg = g_offs[dst], end = g_offs[dst + 1];

    float den = 0.f, ax = 0.f, ay = 0.f;
    int i = beg;
    for (; i < end && (i & 3); i++) {
        int s = __ldg(&g_ebuf[i]);
        float e = LRELU(__ldg(&g_as2[s]) + ad);
        float w = __expf(e);
        float2 hv = __half22float2(__ldg(&g_h2h[(size_t)s * 32 + lane]));
        den += w; ax = fmaf(w, hv.x, ax); ay = fmaf(w, hv.y, ay);
    }
    for (; i + 8 <= end; i += 8) {
        int4 sa = *(const int4*)&g_ebuf[i];
        int4 sb = *(const int4*)&g_ebuf[i + 4];
        float e0 = __ldg(&g_as2[sa.x]);
        float e1 = __ldg(&g_as2[sa.y]);
        float e2 = __ldg(&g_as2[sa.z]);
        float e3 = __ldg(&g_as2[sa.w]);
        float e4 = __ldg(&g_as2[sb.x]);
        float e5 = __ldg(&g_as2[sb.y]);
        float e6 = __ldg(&g_as2[sb.z]);
        float e7 = __ldg(&g_as2[sb.w]);
        __half2 q0 = __ldg(&g_h2h[(size_t)sa.x * 32 + lane]);
        __half2 q1 = __ldg(&g_h2h[(size_t)sa.y * 32 + lane]);
        __half2 q2 = __ldg(&g_h2h[(size_t)sa.z * 32 + lane]);
        __half2 q3 = __ldg(&g_h2h[(size_t)sa.w * 32 + lane]);
        __half2 q4 = __ldg(&g_h2h[(size_t)sb.x * 32 + lane]);
        __half2 q5 = __ldg(&g_h2h[(size_t)sb.y * 32 + lane]);
        __half2 q6 = __ldg(&g_h2h[(size_t)sb.z * 32 + lane]);
        __half2 q7 = __ldg(&g_h2h[(size_t)sb.w * 32 + lane]);
        float w0 = __expf(LRELU(e0 + ad)), w1 = __expf(LRELU(e1 + ad));
        float w2 = __expf(LRELU(e2 + ad)), w3 = __expf(LRELU(e3 + ad));
        float w4 = __expf(LRELU(e4 + ad)), w5 = __expf(LRELU(e5 + ad));
        float w6 = __expf(LRELU(e6 + ad)), w7 = __expf(LRELU(e7 + ad));
        den += ((w0 + w1) + (w2 + w3)) + ((w4 + w5) + (w6 + w7));
        float2 f0 = __half22float2(q0), f1 = __half22float2(q1);
        float2 f2 = __half22float2(q2), f3 = __half22float2(q3);
        float2 f4 = __half22float2(q4), f5 = __half22float2(q5);
        float2 f6 = __half22float2(q6), f7 = __half22float2(q7);
        ax = fmaf(w0, f0.x, ax); ay = fmaf(w0, f0.y, ay);
        ax = fmaf(w1, f1.x, ax); ay = fmaf(w1, f1.y, ay);
        ax = fmaf(w2, f2.x, ax); ay = fmaf(w2, f2.y, ay);
        ax = fmaf(w3, f3.x, ax); ay = fmaf(w3, f3.y, ay);
        ax = fmaf(w4, f4.x, ax); ay = fmaf(w4, f4.y, ay);
        ax = fmaf(w5, f5.x, ax); ay = fmaf(w5, f5.y, ay);
        ax = fmaf(w6, f6.x, ax); ay = fmaf(w6, f6.y, ay);
        ax = fmaf(w7, f7.x, ax); ay = fmaf(w7, f7.y, ay);
    }
    for (; i + 4 <= end; i += 4) {
        int4 ss = *(const int4*)&g_ebuf[i];
        float e0 = __ldg(&g_as2[ss.x]);
        float e1 = __ldg(&g_as2[ss.y]);
        float e2 = __ldg(&g_as2[ss.z]);
        float e3 = __ldg(&g_as2[ss.w]);
        __half2 q0 = __ldg(&g_h2h[(size_t)ss.x * 32 + lane]);
        __half2 q1 = __ldg(&g_h2h[(size_t)ss.y * 32 + lane]);
        __half2 q2 = __ldg(&g_h2h[(size_t)ss.z * 32 + lane]);
        __half2 q3 = __ldg(&g_h2h[(size_t)ss.w * 32 + lane]);
        float w0 = __expf(LRELU(e0 + ad)), w1 = __expf(LRELU(e1 + ad));
        float w2 = __expf(LRELU(e2 + ad)), w3 = __expf(LRELU(e3 + ad));
        den += (w0 + w1) + (w2 + w3);
        float2 f0 = __half22float2(q0), f1 = __half22float2(q1);
        float2 f2 = __half22float2(q2), f3 = __half22float2(q3);
        ax = fmaf(w0, f0.x, ax); ay = fmaf(w0, f0.y, ay);
        ax = fmaf(w1, f1.x, ax); ay = fmaf(w1, f1.y, ay);
        ax = fmaf(w2, f2.x, ax); ay = fmaf(w2, f2.y, ay);
        ax = fmaf(w3, f3.x, ax); ay = fmaf(w3, f3.y, ay);
    }
    for (; i < end; i++) {
        int s = __ldg(&g_ebuf[i]);
        float e = LRELU(__ldg(&g_as2[s]) + ad);
        float w = __expf(e);
        float2 hv = __half22float2(__ldg(&g_h2h[(size_t)s * 32 + lane]));
        den += w; ax = fmaf(w, hv.x, ax); ay = fmaf(w, hv.y, ay);
    }
    float inv = 1.f / (den + 1e-16f);
    int c0 = lane * 2;
    float v0 = fmaf(ax, inv, bias2[c0]);
    float v1 = fmaf(ay, inv, bias2[c0 + 1]);

    float m = fmaxf(v0, v1);
    #pragma unroll
    for (int o = 16; o >= 1; o >>= 1) m = fmaxf(m, __shfl_xor_sync(0xffffffffu, m, o));
    float se = __expf(v0 - m) + __expf(v1 - m);
    #pragma unroll
    for (int o = 16; o >= 1; o >>= 1) se += __shfl_xor_sync(0xffffffffu, se, o);
    float lse = m + logf(se);

    ((float2*)out)[(size_t)dst * 32 + lane] = make_float2(v0 - lse, v1 - lse);
}

// ---------------- launch ----------------------------------------------------
extern "C" void kernel_launch(void* const* d_in, const int* in_sizes, int n_in,
                              void* d_out, int out_size) {
    const float* x      = (const float*)d_in[0];
    const void*  ei     = d_in[1];
    const float* W1     = (const float*)d_in[2];
    const float* atts1  = (const float*)d_in[3];
    const float* attd1  = (const float*)d_in[4];
    const float* bias1  = (const float*)d_in[5];
    const float* W2     = (const float*)d_in[6];
    const float* atts2  = (const float*)d_in[7];
    const float* attd2  = (const float*)d_in[8];
    const float* bias2  = (const float*)d_in[9];
    float* out = (float*)d_out;

    int N = in_sizes[0] / 256;
    int E = in_sizes[1] / 2;
    int nb = (N + 1023) / 1024;

    // one-time handles (created on the first, non-captured, correctness call;
    // the captured work below is identical on every call)
    static cudaStream_t s2 = nullptr;
    static cudaEvent_t evRoot = nullptr, evG = nullptr;
    if (s2 == nullptr) {
        cudaStreamCreateWithFlags(&s2, cudaStreamNonBlocking);
        cudaEventCreateWithFlags(&evRoot, cudaEventDisableTiming);
        cudaEventCreateWithFlags(&evG, cudaEventDisableTiming);
        cudaFuncSetAttribute(gemm1_wmma_kernel,
                             cudaFuncAttributeMaxDynamicSharedMemorySize, 104448);
    }

    // fork: GEMM chain on s2, CSR chain on the main stream
    cudaEventRecord(evRoot, 0);
    cudaStreamWaitEvent(s2, evRoot, 0);

    wconv_kernel     <<<64, 256, 0, s2>>>(W1);
    gemm1_wmma_kernel<<<(N + 127) / 128, 256, 104448, s2>>>(x, atts1, attd1, N);
    cudaEventRecord(evG, s2);

    zerodetect_kernel<<<(N + 255) / 256, 256>>>((const int*)ei, E, N);
    count_kernel     <<<(E + 255) / 256, 256>>>(ei, E, N);
    scan_block_kernel<<<nb, 1024>>>(N);
    scan_add_kernel  <<<nb, 1024>>>(N, nb);
    scatter_kernel   <<<(E + 255) / 256, 256>>>(ei, E, N);

    // join: agg1 needs both chains
    cudaStreamWaitEvent(0, evG, 0);
    agg1_kernel <<<(N + 7) / 8, 256>>>(bias1, N);
    gemm2_kernel<<<(N + 31) / 32, 256>>>(W2, atts2, attd2, N);
    agg2_kernel <<<(N + 7) / 8, 256>>>(bias2, out, N);
}